// round 1
// baseline (speedup 1.0000x reference)
#include <cuda_runtime.h>
#include <cstdint>

// Problem constants (fixed shapes for this problem instance)
#define GG 32          // graphs
#define NN 8192        // nodes per graph
#define DD 32          // neighbors per node
#define CC (GG * NN)   // 262144 total nodes == max labels
#define TSZ (1 << 20)  // hash table slots (load factor 0.25)

// ---------------- device scratch (static, allowed) ----------------
__device__ int4  g_cred4[(size_t)CC * 9];     // 33 ints padded to 36 per node (37.7MB)
__device__ int   g_table[TSZ];                // slot -> owning node id, or -1
__device__ int   g_nodeslot[CC];              // node -> slot
__device__ int   g_slotlabel[TSZ];            // slot -> dense label
__device__ unsigned g_counter;                // dense label counter
__device__ float g_W[(size_t)CC * GG];        // per-(label, graph) weight sums (32MB); invariant: zero at launch entry/exit
__device__ float g_K[GG * GG];                // accumulated Gram
__device__ int   g_labA[CC];
__device__ int   g_labB[CC];

__device__ __forceinline__ int get_lim(const int* nit) { return nit ? *nit : 3; }

// ---------------- kernels ----------------

__global__ void k_clearK() {
    if (threadIdx.x < GG * GG) g_K[threadIdx.x] = 0.f;
}

__global__ void k_cleartab(const int* nit, int iter) {
    if (iter > get_lim(nit)) return;
    int s = blockIdx.x * 1024 + threadIdx.x;
    g_table[s] = -1;
    if (s == 0) g_counter = 0u;
}

// Initial histogram from init labels (already dense, < 16 here but any < CC works)
__global__ void k_hist_init(const int* __restrict__ lab, const float* __restrict__ w) {
    int node = blockIdx.x * 256 + threadIdx.x;
    int l = lab[node];
    int g = node >> 13;   // node / NN
    atomicAdd(&g_W[(size_t)l * GG + g], w[node]);
}

// gather neighbor labels (smem), bitonic-sort in regs, hash, exact hash-table insert
__global__ void __launch_bounds__(512)
k_relabel(const int* __restrict__ nbr, const int* __restrict__ inputLab,
          int srcSel, const int* nit, int iter) {
    if (iter > get_lim(nit)) return;
    __shared__ int slab[NN];  // 32KB: this graph's labels
    const int blocksPerGraph = NN / 512;  // 16
    int g = blockIdx.x / blocksPerGraph;
    int nbase = (blockIdx.x % blocksPerGraph) * 512;
    const int* prev = (srcSel == 0) ? inputLab : (srcSel == 1 ? g_labA : g_labB);
    const int* gl = prev + g * NN;
    for (int i = threadIdx.x; i < NN; i += 512) slab[i] = gl[i];
    __syncthreads();

    int n = nbase + threadIdx.x;
    int node = g * NN + n;
    int own = slab[n];

    int v[32];
    const int4* np = (const int4*)(nbr + (size_t)node * DD);
#pragma unroll
    for (int q = 0; q < 8; q++) {
        int4 t = np[q];
        v[q * 4 + 0] = slab[t.x];
        v[q * 4 + 1] = slab[t.y];
        v[q * 4 + 2] = slab[t.z];
        v[q * 4 + 3] = slab[t.w];
    }

    // bitonic sort, ascending, fully unrolled (all indices compile-time)
#pragma unroll
    for (int k = 2; k <= 32; k <<= 1) {
#pragma unroll
        for (int j = k >> 1; j > 0; j >>= 1) {
#pragma unroll
            for (int i = 0; i < 32; i++) {
                int l = i ^ j;
                if (l > i) {
                    int a = v[i], b = v[l];
                    int lo = min(a, b), hi = max(a, b);
                    if ((i & k) == 0) { v[i] = lo; v[l] = hi; }
                    else              { v[i] = hi; v[l] = lo; }
                }
            }
        }
    }

    // FNV-1a 64-bit over (own, v[0..31])
    unsigned long long h = 1469598103934665603ULL;
    h = (h ^ (unsigned)own) * 1099511628211ULL;
#pragma unroll
    for (int i = 0; i < 32; i++) h = (h ^ (unsigned)v[i]) * 1099511628211ULL;
    h ^= h >> 33;

    // publish credential (9 x int4 = 36 ints, last 3 are zero padding)
    int4* cp = g_cred4 + (size_t)node * 9;
    cp[0] = make_int4(own, v[0], v[1], v[2]);
#pragma unroll
    for (int q = 1; q < 8; q++)
        cp[q] = make_int4(v[4 * q - 1], v[4 * q], v[4 * q + 1], v[4 * q + 2]);
    cp[8] = make_int4(v[31], 0, 0, 0);
    __threadfence();  // credential visible before slot claim

    unsigned s = (unsigned)h & (TSZ - 1);
    for (;;) {
        int prevOwner = atomicCAS(&g_table[s], -1, node);
        if (prevOwner == -1) { g_nodeslot[node] = (int)s; break; }
        // exact compare against owner's credential (rare path)
        const int4* op = g_cred4 + (size_t)prevOwner * 9;
        int4 t0 = __ldcg(op);
        bool eq = (t0.x == own) & (t0.y == v[0]) & (t0.z == v[1]) & (t0.w == v[2]);
#pragma unroll
        for (int q = 1; q < 8; q++) {
            int4 u = __ldcg(op + q);
            eq = eq & (u.x == v[4 * q - 1]) & (u.y == v[4 * q]) &
                      (u.z == v[4 * q + 1]) & (u.w == v[4 * q + 2]);
        }
        eq = eq & (__ldcg(op + 8).x == v[31]);
        if (eq) { g_nodeslot[node] = (int)s; break; }
        s = (s + 1) & (TSZ - 1);
    }
}

// dense label assignment, block-aggregated counter
__global__ void k_assign(const int* nit, int iter) {
    if (iter > get_lim(nit)) return;
    int s = blockIdx.x * 1024 + threadIdx.x;
    bool claimed = (g_table[s] != -1);
    unsigned b = __ballot_sync(0xffffffffu, claimed);
    int warp = threadIdx.x >> 5, lane = threadIdx.x & 31;
    __shared__ int wcnt[32];
    __shared__ int woff[32];
    __shared__ int base;
    if (lane == 0) wcnt[warp] = __popc(b);
    __syncthreads();
    if (threadIdx.x == 0) {
        int tot = 0;
        for (int i = 0; i < 32; i++) { woff[i] = tot; tot += wcnt[i]; }
        base = (int)atomicAdd(&g_counter, (unsigned)tot);
    }
    __syncthreads();
    if (claimed)
        g_slotlabel[s] = base + woff[warp] + __popc(b & ((1u << lane) - 1u));
}

// write new labels + histogram into W
__global__ void k_hist(const float* __restrict__ w, int dstSel, const int* nit, int iter) {
    if (iter > get_lim(nit)) return;
    int node = blockIdx.x * 256 + threadIdx.x;
    int lab = g_slotlabel[g_nodeslot[node]];
    if (dstSel == 1) g_labA[node] = lab; else g_labB[node] = lab;
    int g = node >> 13;
    atomicAdd(&g_W[(size_t)lab * GG + g], w[node]);
}

// K += W^T W (32x32 Gram over CC rows), fused with zeroing W
__global__ void __launch_bounds__(256)
k_gram(const int* nit, int iter) {
    if (iter > get_lim(nit)) return;
    int gw = (blockIdx.x * 256 + threadIdx.x) >> 5;  // global warp id
    int lane = threadIdx.x & 31;
    const int totalWarps = (256 * 256) / 32;  // 2048
    float acc[32];
#pragma unroll
    for (int j = 0; j < 32; j++) acc[j] = 0.f;
    for (int r = gw; r < CC; r += totalWarps) {
        float x = g_W[(size_t)r * 32 + lane];
        if (__ballot_sync(0xffffffffu, x != 0.f)) {
#pragma unroll
            for (int j = 0; j < 32; j++)
                acc[j] = fmaf(x, __shfl_sync(0xffffffffu, x, j), acc[j]);
            g_W[(size_t)r * 32 + lane] = 0.f;  // restore zero-invariant
        }
    }
    __shared__ float S[1024];
    for (int i = threadIdx.x; i < 1024; i += 256) S[i] = 0.f;
    __syncthreads();
#pragma unroll
    for (int j = 0; j < 32; j++) atomicAdd(&S[lane * 32 + j], acc[j]);
    __syncthreads();
    for (int i = threadIdx.x; i < 1024; i += 256)
        if (S[i] != 0.f) atomicAdd(&g_K[i], S[i]);
}

__global__ void k_norm(float* __restrict__ out) {
    int t = threadIdx.x;  // 1024 threads
    int i = t >> 5, j = t & 31;
    float dij = sqrtf(g_K[i * 32 + i] * g_K[j * 32 + j]);
    out[t] = g_K[t] / dij;
}

// ---------------- host launcher ----------------
extern "C" void kernel_launch(void* const* d_in, const int* in_sizes, int n_in,
                              void* d_out, int out_size) {
    const int*   nbr = (const int*)d_in[0];
    const int*   il  = (const int*)d_in[1];
    const float* wts = (const float*)d_in[2];
    const int*   nit = (n_in >= 4) ? (const int*)d_in[3] : nullptr;
    float* out = (float*)d_out;

    k_clearK<<<1, 1024>>>();
    k_hist_init<<<CC / 256, 256>>>(il, wts);
    k_gram<<<256, 256>>>(nit, 0);

    // iteration 1: src = input labels, dst = A
    // iteration 2: src = A,            dst = B
    // iteration 3: src = B,            dst = A
    const int srcSel[3] = {0, 1, 2};
    const int dstSel[3] = {1, 2, 1};
    for (int it = 1; it <= 3; ++it) {
        k_cleartab<<<TSZ / 1024, 1024>>>(nit, it);
        k_relabel<<<(GG * NN) / 512, 512>>>(nbr, il, srcSel[it - 1], nit, it);
        k_assign<<<TSZ / 1024, 1024>>>(nit, it);
        k_hist<<<CC / 256, 256>>>(wts, dstSel[it - 1], nit, it);
        k_gram<<<256, 256>>>(nit, it);
    }
    k_norm<<<1, 1024>>>(out);
    (void)in_sizes; (void)out_size;
}

// round 2
// speedup vs baseline: 2.8558x; 2.8558x over previous
#include <cuda_runtime.h>
#include <cstdint>

#define GG 32          // graphs
#define NN 8192        // nodes per graph
#define DD 32          // neighbors per node
#define CC (GG * NN)   // 262144 total nodes == max labels
#define TSZ (1 << 20)  // hash table slots

// ---------------- device scratch ----------------
__device__ ulonglong2 g_sig[CC];              // 128-bit multiset signature per node (4MB)
__device__ int   g_table[TSZ];                // slot -> owning node id, or -1 (4MB)
__device__ int   g_nodeslot[CC];              // node -> slot
__device__ int   g_slotlabel[TSZ];            // slot -> dense label
__device__ unsigned g_cnt[4];                 // per-iteration dense label counts
__device__ float g_W[(size_t)CC * GG];        // (label, graph) weights (32MB); zero-invariant
__device__ float g_K[GG * GG];
__device__ int   g_labA[CC];
__device__ int   g_labB[CC];

__device__ __forceinline__ int get_lim(const int* nit) { return nit ? *nit : 3; }

__device__ __forceinline__ unsigned mix32(unsigned x) {
    x ^= x >> 16; x *= 0x7feb352du;
    x ^= x >> 15; x *= 0x846ca68bu;
    x ^= x >> 16;
    return x;
}
__device__ __forceinline__ unsigned long long mix64(unsigned long long x) {
    x ^= x >> 30; x *= 0xbf58476d1ce4e5b9ULL;
    x ^= x >> 27; x *= 0x94d049bb133111ebULL;
    x ^= x >> 31;
    return x;
}

// ---------------- kernels ----------------

// init: clear K, reset per-iter counters, track max init label, initial histogram
__global__ void k_init(const int* __restrict__ il, const float* __restrict__ w) {
    int t = blockIdx.x * 256 + threadIdx.x;
    if (t < GG * GG) g_K[t] = 0.f;
    if (t >= 1 && t <= 3) g_cnt[t] = 0u;

    int l = il[t];
    // warp-reduce max(l+1) -> g_cnt[0]  (bound for gram0's row scan)
    unsigned m = (unsigned)(l + 1);
#pragma unroll
    for (int o = 16; o > 0; o >>= 1)
        m = max(m, __shfl_xor_sync(0xffffffffu, m, o));
    if ((threadIdx.x & 31) == 0) atomicMax(&g_cnt[0], m);

    atomicAdd(&g_W[(size_t)l * GG + (t >> 13)], w[t]);
}

// relabel: premix labels in smem, commutative 128-bit signature, exact hash-table insert
__global__ void __launch_bounds__(512)
k_relabel(const int* __restrict__ nbr, const int* __restrict__ inputLab,
          int srcSel, const int* nit, int iter) {
    if (iter > get_lim(nit)) return;
    __shared__ unsigned sm[NN];  // 32KB premixed labels of this graph
    int g = blockIdx.x >> 4;               // 16 blocks per graph
    int nbase = (blockIdx.x & 15) * 512;
    const int* prev = (srcSel == 0) ? inputLab : (srcSel == 1 ? g_labA : g_labB);
    const int* gl = prev + g * NN;
    for (int i = threadIdx.x; i < NN; i += 512)
        sm[i] = mix32((unsigned)gl[i]);
    __syncthreads();

    int n = nbase + threadIdx.x;
    int node = g * NN + n;

    unsigned long long A = mix64((unsigned long long)(unsigned)gl[n] + 0x9E3779B97F4A7C15ULL);
    unsigned long long s1 = A;
    unsigned long long s2 = mix64(A);

    const int4* np = (const int4*)(nbr + (size_t)node * DD);
#pragma unroll
    for (int q = 0; q < 8; q++) {
        int4 t = np[q];
        unsigned m0 = sm[t.x], m1 = sm[t.y], m2 = sm[t.z], m3 = sm[t.w];
        s1 += m0; s2 += (unsigned long long)m0 * m0;
        s1 += m1; s2 += (unsigned long long)m1 * m1;
        s1 += m2; s2 += (unsigned long long)m2 * m2;
        s1 += m3; s2 += (unsigned long long)m3 * m3;
    }

    g_sig[node] = make_ulonglong2(s1, s2);
    __threadfence();  // signature visible before slot claim

    unsigned long long h = mix64(s1 ^ (s2 * 0x9E3779B97F4A7C15ULL));
    unsigned s = (unsigned)h & (TSZ - 1);
    for (;;) {
        int prevOwner = atomicCAS(&g_table[s], -1, node);
        if (prevOwner == -1) { g_nodeslot[node] = (int)s; break; }
        const unsigned long long* op = &g_sig[prevOwner].x;
        unsigned long long o1 = __ldcg(op);
        unsigned long long o2 = __ldcg(op + 1);
        if (o1 == s1 && o2 == s2) { g_nodeslot[node] = (int)s; break; }
        s = (s + 1) & (TSZ - 1);
    }
}

// dense label assignment with block-aggregated counter (into g_cnt[iter])
__global__ void k_assign(const int* nit, int iter) {
    if (iter > get_lim(nit)) return;
    int s = blockIdx.x * 1024 + threadIdx.x;
    bool claimed = (g_table[s] != -1);
    unsigned b = __ballot_sync(0xffffffffu, claimed);
    int warp = threadIdx.x >> 5, lane = threadIdx.x & 31;
    __shared__ int wcnt[32];
    __shared__ int woff[32];
    __shared__ int base;
    if (lane == 0) wcnt[warp] = __popc(b);
    __syncthreads();
    if (threadIdx.x == 0) {
        int tot = 0;
        for (int i = 0; i < 32; i++) { woff[i] = tot; tot += wcnt[i]; }
        base = (int)atomicAdd(&g_cnt[iter], (unsigned)tot);
    }
    __syncthreads();
    if (claimed)
        g_slotlabel[s] = base + woff[warp] + __popc(b & ((1u << lane) - 1u));
}

// write new labels + histogram into W
__global__ void k_hist(const float* __restrict__ w, int dstSel, const int* nit, int iter) {
    if (iter > get_lim(nit)) return;
    int node = blockIdx.x * 256 + threadIdx.x;
    int lab = g_slotlabel[g_nodeslot[node]];
    if (dstSel == 1) g_labA[node] = lab; else g_labB[node] = lab;
    atomicAdd(&g_W[(size_t)lab * GG + (node >> 13)], w[node]);
}

// K += W^T W over nlab rows; re-zero W; also clears the hash table for the next iteration
__global__ void __launch_bounds__(256)
k_gram(const int* nit, int iter) {
    if (iter > get_lim(nit)) return;
    int tid = blockIdx.x * 256 + threadIdx.x;   // 65536 threads

    // clear hash table (for next relabel); 4 x int4 per thread = 1M ints
    int4* tp = (int4*)g_table;
#pragma unroll
    for (int q = 0; q < 4; q++)
        tp[tid + q * 65536] = make_int4(-1, -1, -1, -1);

    int nlab = (int)g_cnt[iter];
    int gw = tid >> 5, lane = tid & 31;
    const int totW = 2048;  // (256*256)/32

    float acc[32];
#pragma unroll
    for (int j = 0; j < 32; j++) acc[j] = 0.f;
    float accD = 0.f;  // diagonal fast path: rows with exactly one nonzero graph

    for (int r = gw * 8; r < nlab; r += totW * 8) {
        float x[8];
#pragma unroll
        for (int k = 0; k < 8; k++) {
            int rr = r + k;
            x[k] = (rr < nlab) ? g_W[(size_t)rr * 32 + lane] : 0.f;
        }
#pragma unroll
        for (int k = 0; k < 8; k++) {
            unsigned bz = __ballot_sync(0xffffffffu, x[k] != 0.f);
            if (!bz) continue;
            if (__popc(bz) == 1) {
                accD += x[k] * x[k];   // only the owning lane has x != 0
            } else {
#pragma unroll
                for (int j = 0; j < 32; j++)
                    acc[j] = fmaf(x[k], __shfl_sync(0xffffffffu, x[k], j), acc[j]);
            }
            g_W[(size_t)(r + k) * 32 + lane] = 0.f;  // restore zero-invariant
        }
    }

    __shared__ float S[1024];
    for (int i = threadIdx.x; i < 1024; i += 256) S[i] = 0.f;
    __syncthreads();
#pragma unroll
    for (int j = 0; j < 32; j++)
        if (acc[j] != 0.f) atomicAdd(&S[lane * 32 + j], acc[j]);
    if (accD != 0.f) atomicAdd(&S[lane * 33], accD);  // K[lane][lane]
    __syncthreads();
    for (int i = threadIdx.x; i < 1024; i += 256)
        if (S[i] != 0.f) atomicAdd(&g_K[i], S[i]);
}

__global__ void k_norm(float* __restrict__ out) {
    int t = threadIdx.x;  // 1024 threads
    int i = t >> 5, j = t & 31;
    float dij = sqrtf(g_K[i * 32 + i] * g_K[j * 32 + j]);
    out[t] = g_K[t] / dij;
}

// ---------------- host launcher ----------------
extern "C" void kernel_launch(void* const* d_in, const int* in_sizes, int n_in,
                              void* d_out, int out_size) {
    const int*   nbr = (const int*)d_in[0];
    const int*   il  = (const int*)d_in[1];
    const float* wts = (const float*)d_in[2];
    const int*   nit = (n_in >= 4) ? (const int*)d_in[3] : nullptr;
    float* out = (float*)d_out;

    k_init<<<CC / 256, 256>>>(il, wts);
    k_gram<<<256, 256>>>(nit, 0);   // also clears hash table for iter 1

    const int srcSel[3] = {0, 1, 2};
    const int dstSel[3] = {1, 2, 1};
    for (int it = 1; it <= 3; ++it) {
        k_relabel<<<(GG * NN) / 512, 512>>>(nbr, il, srcSel[it - 1], nit, it);
        k_assign<<<TSZ / 1024, 1024>>>(nit, it);
        k_hist<<<CC / 256, 256>>>(wts, dstSel[it - 1], nit, it);
        k_gram<<<256, 256>>>(nit, it);   // also clears hash table for next iter
    }
    k_norm<<<1, 1024>>>(out);
    (void)in_sizes; (void)out_size;
}

// round 3
// speedup vs baseline: 3.3568x; 1.1755x over previous
#include <cuda_runtime.h>
#include <cstdint>

#define GG 32          // graphs
#define NN 8192        // nodes per graph
#define DD 32          // neighbors per node
#define CC (GG * NN)   // 262144 total nodes == label space
#define TSZ (1 << 20)  // hash table slots

#define LABMASK 0x7FFFFull            // low 19 bits: node_id+1
#define TAGMASK (~0x7FFFFull)         // high 45 bits: hash tag

// ---------------- device scratch ----------------
__device__ unsigned long long g_table[TSZ];   // (tag<<19)|(node+1), 0 = empty (8MB)
__device__ unsigned g_cnt0;                   // max init label + 1 (bound for gram0 scan)
__device__ float g_W[(size_t)CC * GG];        // (label, graph) weights (32MB); zero-invariant
__device__ float g_K[GG * GG];
__device__ int   g_labA[CC];
__device__ int   g_labB[CC];

__device__ __forceinline__ int get_lim(const int* nit) { return nit ? *nit : 3; }

__device__ __forceinline__ unsigned mix32(unsigned x) {
    x ^= x >> 16; x *= 0x7feb352du;
    x ^= x >> 15; x *= 0x846ca68bu;
    x ^= x >> 16;
    return x;
}
__device__ __forceinline__ unsigned long long mix64(unsigned long long x) {
    x ^= x >> 30; x *= 0xbf58476d1ce4e5b9ULL;
    x ^= x >> 27; x *= 0x94d049bb133111ebULL;
    x ^= x >> 31;
    return x;
}

// ---------------- kernels ----------------

// init: clear K, track max init label, initial histogram into W
__global__ void k_init(const int* __restrict__ il, const float* __restrict__ w) {
    int t = blockIdx.x * 256 + threadIdx.x;
    if (t < GG * GG) g_K[t] = 0.f;

    int l = il[t];
    unsigned m = (unsigned)(l + 1);
#pragma unroll
    for (int o = 16; o > 0; o >>= 1)
        m = max(m, __shfl_xor_sync(0xffffffffu, m, o));
    if ((threadIdx.x & 31) == 0) atomicMax(&g_cnt0, m);

    atomicAdd(&g_W[(size_t)l * GG + (t >> 13)], w[t]);
}

// fused relabel + label-resolve + histogram:
//   premix labels in smem, commutative 128-bit signature -> 64-bit hash,
//   hash-table entry packs (tag | node_id+1) so losers get the winner's
//   label from the CAS return value. No counter, no second pass.
__global__ void __launch_bounds__(512)
k_relabel(const int* __restrict__ nbr, const int* __restrict__ inputLab,
          const float* __restrict__ wts, int srcSel, int dstSel,
          const int* nit, int iter) {
    if (iter > get_lim(nit)) return;
    __shared__ unsigned sm[NN];  // 32KB premixed labels of this graph
    int g = blockIdx.x >> 4;                // 16 blocks per graph
    int nbase = (blockIdx.x & 15) * 512;
    const int* prev = (srcSel == 0) ? inputLab : (srcSel == 1 ? g_labA : g_labB);
    const int* gl = prev + g * NN;
    for (int i = threadIdx.x; i < NN; i += 512)
        sm[i] = mix32((unsigned)gl[i]);
    __syncthreads();

    int n = nbase + threadIdx.x;
    int node = g * NN + n;

    unsigned long long A = mix64((unsigned long long)sm[n] + 0x9E3779B97F4A7C15ULL);
    unsigned long long s1 = A;
    unsigned long long s2 = mix64(A);

    const int4* np = (const int4*)(nbr + (size_t)node * DD);
#pragma unroll
    for (int q = 0; q < 8; q++) {
        int4 t = np[q];
        unsigned m0 = sm[t.x], m1 = sm[t.y], m2 = sm[t.z], m3 = sm[t.w];
        s1 += m0; s2 += (unsigned long long)m0 * m0;
        s1 += m1; s2 += (unsigned long long)m1 * m1;
        s1 += m2; s2 += (unsigned long long)m2 * m2;
        s1 += m3; s2 += (unsigned long long)m3 * m3;
    }

    unsigned long long h = mix64(s1 ^ (s2 * 0x9E3779B97F4A7C15ULL));
    unsigned long long cand = (h & TAGMASK) | (unsigned long long)(node + 1);
    unsigned s = (unsigned)h & (TSZ - 1);

    int lab;
    for (;;) {
        unsigned long long old = atomicCAS(&g_table[s], 0ull, cand);
        if (old == 0ull) { lab = node; break; }                       // winner: own id
        if (((old ^ cand) & TAGMASK) == 0ull) {                       // same credential
            lab = (int)(old & LABMASK) - 1;                           // winner's id
            break;
        }
        s = (s + 1) & (TSZ - 1);
    }

    if (dstSel == 1) g_labA[node] = lab; else g_labB[node] = lab;
    atomicAdd(&g_W[((unsigned)lab << 5) + (unsigned)g], wts[node]);
}

// K += W^T W over the active rows; re-zero nonzero W rows; clear hash table
// for the next iteration (skipped on the final iteration).
__global__ void __launch_bounds__(256)
k_gram(const int* nit, int iter) {
    int lim = get_lim(nit);
    if (iter > lim) return;
    int tid = blockIdx.x * 256 + threadIdx.x;   // 65536 threads

    if (iter < lim) {   // clear hash table for the next relabel (8MB)
        int4* tp = (int4*)g_table;
#pragma unroll
        for (int q = 0; q < 8; q++)
            tp[tid + q * 65536] = make_int4(0, 0, 0, 0);
    }

    int nlab = (iter == 0) ? (int)g_cnt0 : CC;
    int gw = tid >> 5, lane = tid & 31;
    const int totW = 2048;

    float acc[32];
#pragma unroll
    for (int j = 0; j < 32; j++) acc[j] = 0.f;
    float accD = 0.f;  // fast path: rows with exactly one nonzero graph

    for (int r = gw * 8; r < nlab; r += totW * 8) {
        float x[8];
#pragma unroll
        for (int k = 0; k < 8; k++) {
            int rr = r + k;
            x[k] = (rr < nlab) ? g_W[(size_t)rr * 32 + lane] : 0.f;
        }
#pragma unroll
        for (int k = 0; k < 8; k++) {
            unsigned bz = __ballot_sync(0xffffffffu, x[k] != 0.f);
            if (!bz) continue;
            if (__popc(bz) == 1) {
                accD += x[k] * x[k];
            } else {
#pragma unroll
                for (int j = 0; j < 32; j++)
                    acc[j] = fmaf(x[k], __shfl_sync(0xffffffffu, x[k], j), acc[j]);
            }
            g_W[(size_t)(r + k) * 32 + lane] = 0.f;  // restore zero-invariant
        }
    }

    __shared__ float S[1024];
    for (int i = threadIdx.x; i < 1024; i += 256) S[i] = 0.f;
    __syncthreads();
#pragma unroll
    for (int j = 0; j < 32; j++)
        if (acc[j] != 0.f) atomicAdd(&S[lane * 32 + j], acc[j]);
    if (accD != 0.f) atomicAdd(&S[lane * 33], accD);
    __syncthreads();
    for (int i = threadIdx.x; i < 1024; i += 256)
        if (S[i] != 0.f) atomicAdd(&g_K[i], S[i]);
}

__global__ void k_norm(float* __restrict__ out) {
    int t = threadIdx.x;  // 1024 threads
    int i = t >> 5, j = t & 31;
    float dij = sqrtf(g_K[i * 32 + i] * g_K[j * 32 + j]);
    out[t] = g_K[t] / dij;
}

// ---------------- host launcher ----------------
extern "C" void kernel_launch(void* const* d_in, const int* in_sizes, int n_in,
                              void* d_out, int out_size) {
    const int*   nbr = (const int*)d_in[0];
    const int*   il  = (const int*)d_in[1];
    const float* wts = (const float*)d_in[2];
    const int*   nit = (n_in >= 4) ? (const int*)d_in[3] : nullptr;
    float* out = (float*)d_out;

    k_init<<<CC / 256, 256>>>(il, wts);
    k_gram<<<256, 256>>>(nit, 0);   // gram of init histogram + table clear

    const int srcSel[3] = {0, 1, 2};
    const int dstSel[3] = {1, 2, 1};
    for (int it = 1; it <= 3; ++it) {
        k_relabel<<<(GG * NN) / 512, 512>>>(nbr, il, wts,
                                            srcSel[it - 1], dstSel[it - 1], nit, it);
        k_gram<<<256, 256>>>(nit, it);
    }
    k_norm<<<1, 1024>>>(out);
    (void)in_sizes; (void)out_size;
}

// round 4
// speedup vs baseline: 3.6080x; 1.0748x over previous
#include <cuda_runtime.h>
#include <cstdint>

#define GG 32          // graphs
#define NN 8192        // nodes per graph
#define DD 32          // neighbors per node
#define CC (GG * NN)   // 262144 total nodes == label space
#define TSZ (1 << 20)  // hash table slots

#define LABMASK 0x7FFFFull            // low 19 bits: node_id+1
#define TAGMASK (~0x7FFFFull)         // high 45 bits: hash tag

// ---------------- device scratch ----------------
__device__ unsigned long long g_table[TSZ];   // (tag)|(node+1), 0 = empty (8MB); zero-invariant
__device__ float g_W[(size_t)CC * GG];        // (label, graph) weights (32MB); zero-invariant
__device__ float g_K[GG * GG];
__device__ int   g_labA[CC];
__device__ int   g_labB[CC];

__device__ __forceinline__ int get_lim(const int* nit) { return nit ? *nit : 3; }

__device__ __forceinline__ unsigned mix32(unsigned x) {
    x ^= x >> 16; x *= 0x7feb352du;
    x ^= x >> 15; x *= 0x846ca68bu;
    x ^= x >> 16;
    return x;
}
__device__ __forceinline__ unsigned long long mix64(unsigned long long x) {
    x ^= x >> 30; x *= 0xbf58476d1ce4e5b9ULL;
    x ^= x >> 27; x *= 0x94d049bb133111ebULL;
    x ^= x >> 31;
    return x;
}

// ---------------- kernels ----------------

// init: clear K, initial histogram into W
__global__ void k_init(const int* __restrict__ il, const float* __restrict__ w) {
    int t = blockIdx.x * 256 + threadIdx.x;
    if (t < GG * GG) g_K[t] = 0.f;
    int l = il[t];
    atomicAdd(&g_W[((size_t)(unsigned)l << 5) + (t >> 13)], w[t]);
}

// fused relabel + label-resolve + histogram:
//   premix labels in smem, commutative 128-bit signature -> 64-bit hash,
//   hash-table entry packs (tag | node_id+1): losers read the winner's
//   label straight from the CAS return value.
__global__ void __launch_bounds__(512)
k_relabel(const int* __restrict__ nbr, const int* __restrict__ inputLab,
          const float* __restrict__ wts, int srcSel, int dstSel,
          const int* nit, int iter) {
    if (iter > get_lim(nit)) return;
    __shared__ unsigned sm[NN];  // 32KB premixed labels of this graph
    int g = blockIdx.x >> 4;                // 16 blocks per graph
    int nbase = (blockIdx.x & 15) * 512;
    const int* prev = (srcSel == 0) ? inputLab : (srcSel == 1 ? g_labA : g_labB);
    const int* gl = prev + g * NN;
    {   // stage + premix via int4 (4 int4 per thread)
        const int4* gl4 = (const int4*)gl;
        uint4* sm4 = (uint4*)sm;
#pragma unroll
        for (int q = 0; q < 4; q++) {
            int i = threadIdx.x + q * 512;
            int4 t = gl4[i];
            sm4[i] = make_uint4(mix32((unsigned)t.x), mix32((unsigned)t.y),
                                mix32((unsigned)t.z), mix32((unsigned)t.w));
        }
    }
    __syncthreads();

    int n = nbase + threadIdx.x;
    int node = g * NN + n;

    // prefetch neighbor indices (MLP=8) before the LDS gathers
    int4 tq[8];
    const int4* np = (const int4*)(nbr + (size_t)node * DD);
#pragma unroll
    for (int q = 0; q < 8; q++) tq[q] = np[q];

    unsigned long long A = mix64((unsigned long long)sm[n] + 0x9E3779B97F4A7C15ULL);
    unsigned long long s1 = A;
    unsigned long long s2 = mix64(A);
#pragma unroll
    for (int q = 0; q < 8; q++) {
        unsigned m0 = sm[tq[q].x], m1 = sm[tq[q].y], m2 = sm[tq[q].z], m3 = sm[tq[q].w];
        s1 += m0; s2 += (unsigned long long)m0 * m0;
        s1 += m1; s2 += (unsigned long long)m1 * m1;
        s1 += m2; s2 += (unsigned long long)m2 * m2;
        s1 += m3; s2 += (unsigned long long)m3 * m3;
    }

    unsigned long long h = mix64(s1 ^ (s2 * 0x9E3779B97F4A7C15ULL));
    unsigned long long cand = (h & TAGMASK) | (unsigned long long)(node + 1);
    unsigned s = (unsigned)h & (TSZ - 1);

    int lab;
    for (;;) {
        unsigned long long old = atomicCAS(&g_table[s], 0ull, cand);
        if (old == 0ull) { lab = node; break; }                  // winner: own id
        if (((old ^ cand) & TAGMASK) == 0ull) {                  // same credential
            lab = (int)(old & LABMASK) - 1;                      // winner's id
            break;
        }
        s = (s + 1) & (TSZ - 1);
    }

    if (dstSel == 1) g_labA[node] = lab; else g_labB[node] = lab;
    atomicAdd(&g_W[((size_t)(unsigned)lab << 5) + (unsigned)g], wts[node]);
}

// per-node Gram: K[g_v][lane] += w_v * W[lab_v][lane]  (warp reads rows coalesced)
// labSel: 0 = input labels, 1 = g_labA, 2 = g_labB
__global__ void __launch_bounds__(256)
k_gramv(const int* __restrict__ inputLab, const float* __restrict__ wts,
        int labSel, const int* nit, int iter) {
    if (iter > get_lim(nit)) return;
    const int* labels = (labSel == 0) ? inputLab : (labSel == 1 ? g_labA : g_labB);
    int g = blockIdx.x >> 5;                 // 32 blocks per graph (1024 blocks total)
    int lane = threadIdx.x & 31;
    int warp = threadIdx.x >> 5;
    int base = blockIdx.x * 256 + warp * 32; // this warp's 32 nodes

    float acc = 0.f;
#pragma unroll 4
    for (int i = 0; i < 32; i++) {
        int v = base + i;
        int lab = labels[v];                 // warp-uniform broadcast load
        float w = wts[v];
        float x = g_W[((size_t)(unsigned)lab << 5) + lane];
        acc = fmaf(w, x, acc);
    }

    __shared__ float S[32];
    if (threadIdx.x < 32) S[threadIdx.x] = 0.f;
    __syncthreads();
    atomicAdd(&S[lane], acc);
    __syncthreads();
    if (threadIdx.x < 32)
        atomicAdd(&g_K[(g << 5) + threadIdx.x], S[threadIdx.x]);
}

// restore invariants: zero each node's own W cell (1MB) + clear hash table (8MB)
__global__ void k_zero(const int* __restrict__ inputLab, int labSel,
                       const int* nit, int iter) {
    if (iter > get_lim(nit)) return;
    int v = blockIdx.x * 256 + threadIdx.x;
    const int* labels = (labSel == 0) ? inputLab : (labSel == 1 ? g_labA : g_labB);
    int lab = labels[v];
    g_W[((size_t)(unsigned)lab << 5) + (v >> 13)] = 0.f;
    int4* tp = (int4*)g_table;               // 524288 int4 total, 2 per thread
    tp[v] = make_int4(0, 0, 0, 0);
    tp[v + CC] = make_int4(0, 0, 0, 0);
}

__global__ void k_norm(float* __restrict__ out) {
    int t = threadIdx.x;  // 1024 threads
    int i = t >> 5, j = t & 31;
    float dij = sqrtf(g_K[i * 32 + i] * g_K[j * 32 + j]);
    out[t] = g_K[t] / dij;
}

// ---------------- host launcher ----------------
extern "C" void kernel_launch(void* const* d_in, const int* in_sizes, int n_in,
                              void* d_out, int out_size) {
    const int*   nbr = (const int*)d_in[0];
    const int*   il  = (const int*)d_in[1];
    const float* wts = (const float*)d_in[2];
    const int*   nit = (n_in >= 4) ? (const int*)d_in[3] : nullptr;
    float* out = (float*)d_out;

    k_init<<<CC / 256, 256>>>(il, wts);
    k_gramv<<<CC / 256, 256>>>(il, wts, 0, nit, 0);
    k_zero<<<CC / 256, 256>>>(il, 0, nit, 0);

    const int srcSel[3] = {0, 1, 2};
    const int dstSel[3] = {1, 2, 1};
    for (int it = 1; it <= 3; ++it) {
        k_relabel<<<(GG * NN) / 512, 512>>>(nbr, il, wts,
                                            srcSel[it - 1], dstSel[it - 1], nit, it);
        k_gramv<<<CC / 256, 256>>>(il, wts, dstSel[it - 1], nit, it);
        k_zero<<<CC / 256, 256>>>(il, dstSel[it - 1], nit, it);
    }
    k_norm<<<1, 1024>>>(out);
    (void)in_sizes; (void)out_size;
}

// round 5
// speedup vs baseline: 5.7063x; 1.5816x over previous
#include <cuda_runtime.h>
#include <cstdint>

#define GG 32          // graphs
#define NN 8192        // nodes per graph
#define DD 32          // neighbors per node
#define CC (GG * NN)   // 262144 total nodes == label space
#define TSZ (1 << 20)  // hash table slots

#define LABMASK 0x7FFFFull            // low 19 bits: node_id+1
#define TAGMASK (~0x7FFFFull)         // high 45 bits: hash tag

// ---------------- device scratch (all zero-invariant across calls) ----------------
__device__ unsigned long long g_table[TSZ];   // (tag)|(node+1), 0 = empty (8MB)
__device__ float g_W[(size_t)CC * GG];        // (label, graph) weights (32MB)
__device__ float g_K[GG * GG];
__device__ int   g_labA[CC];
__device__ int   g_labB[CC];
__device__ unsigned char g_shared[CC];        // 1 = node's class has >1 member

__device__ __forceinline__ int get_lim(const int* nit) { return nit ? *nit : 3; }

__device__ __forceinline__ unsigned mix32(unsigned x) {
    x ^= x >> 16; x *= 0x7feb352du;
    x ^= x >> 15; x *= 0x846ca68bu;
    x ^= x >> 16;
    return x;
}
__device__ __forceinline__ unsigned long long mix64(unsigned long long x) {
    x ^= x >> 30; x *= 0xbf58476d1ce4e5b9ULL;
    x ^= x >> 27; x *= 0x94d049bb133111ebULL;
    x ^= x >> 31;
    return x;
}

// ---------------- kernels ----------------

// init: clear K + per-block smem histogram of init labels into W
__global__ void __launch_bounds__(256)
k_init(const int* __restrict__ il, const float* __restrict__ w) {
    __shared__ float hist[4096];
    int t = blockIdx.x * 256 + threadIdx.x;
    for (int i = threadIdx.x; i < 4096; i += 256) hist[i] = 0.f;
    if (t < GG * GG) g_K[t] = 0.f;
    __syncthreads();

    int l = il[t];
    float wv = w[t];
    if ((unsigned)l < 4096u) atomicAdd(&hist[l], wv);
    else atomicAdd(&g_W[((size_t)(unsigned)l << 5) + (t >> 13)], wv);
    __syncthreads();

    int g = t >> 13;   // block covers 256 nodes of one graph
    for (int i = threadIdx.x; i < 4096; i += 256) {
        float v = hist[i];
        if (v != 0.f) atomicAdd(&g_W[((size_t)i << 5) + g], v);
    }
}

// fused relabel + label-resolve + histogram + shared-class flagging
__global__ void __launch_bounds__(512)
k_relabel(const int* __restrict__ nbr, const int* __restrict__ inputLab,
          const float* __restrict__ wts, int srcSel, int dstSel,
          const int* nit, int iter) {
    if (iter > get_lim(nit)) return;
    __shared__ unsigned sm[NN];  // 32KB premixed labels of this graph
    int g = blockIdx.x >> 4;                // 16 blocks per graph
    int nbase = (blockIdx.x & 15) * 512;
    const int* prev = (srcSel == 0) ? inputLab : (srcSel == 1 ? g_labA : g_labB);
    const int* gl = prev + g * NN;
    {   // stage + premix via int4
        const int4* gl4 = (const int4*)gl;
        uint4* sm4 = (uint4*)sm;
#pragma unroll
        for (int q = 0; q < 4; q++) {
            int i = threadIdx.x + q * 512;
            int4 t = gl4[i];
            sm4[i] = make_uint4(mix32((unsigned)t.x), mix32((unsigned)t.y),
                                mix32((unsigned)t.z), mix32((unsigned)t.w));
        }
    }
    __syncthreads();

    int n = nbase + threadIdx.x;
    int node = g * NN + n;

    int4 tq[8];
    const int4* np = (const int4*)(nbr + (size_t)node * DD);
#pragma unroll
    for (int q = 0; q < 8; q++) tq[q] = np[q];

    unsigned long long A = mix64((unsigned long long)sm[n] + 0x9E3779B97F4A7C15ULL);
    unsigned long long s1 = A;
    unsigned long long s2 = mix64(A);
#pragma unroll
    for (int q = 0; q < 8; q++) {
        unsigned m0 = sm[tq[q].x], m1 = sm[tq[q].y], m2 = sm[tq[q].z], m3 = sm[tq[q].w];
        s1 += m0; s2 += (unsigned long long)m0 * m0;
        s1 += m1; s2 += (unsigned long long)m1 * m1;
        s1 += m2; s2 += (unsigned long long)m2 * m2;
        s1 += m3; s2 += (unsigned long long)m3 * m3;
    }

    unsigned long long h = mix64(s1 ^ (s2 * 0x9E3779B97F4A7C15ULL));
    unsigned long long cand = (h & TAGMASK) | (unsigned long long)(node + 1);
    unsigned s = (unsigned)h & (TSZ - 1);

    int lab;
    for (;;) {
        unsigned long long old = atomicCAS(&g_table[s], 0ull, cand);
        if (old == 0ull) { lab = node; break; }                  // winner: own id
        if (((old ^ cand) & TAGMASK) == 0ull) {                  // matched credential
            lab = (int)(old & LABMASK) - 1;                      // winner's id
            g_shared[node] = 1;                                  // class has >1 member
            g_shared[lab] = 1;
            break;
        }
        s = (s + 1) & (TSZ - 1);
    }

    if (dstSel == 1) g_labA[node] = lab; else g_labB[node] = lab;
    atomicAdd(&g_W[((size_t)(unsigned)lab << 5) + (unsigned)g], wts[node]);
}

// per-node Gram with singleton fast path:
//   unflagged node (singleton class): K[g][g] += w^2 (no W read)
//   flagged node: K[g][:] += w * W[lab][:]  (batched row reads, MLP=4)
__global__ void __launch_bounds__(256)
k_gramv(const int* __restrict__ inputLab, const float* __restrict__ wts,
        int labSel, int useShared, const int* nit, int iter) {
    if (iter > get_lim(nit)) return;
    const int* labels = (labSel == 0) ? inputLab : (labSel == 1 ? g_labA : g_labB);
    int g = blockIdx.x >> 5;                  // 32 blocks per graph
    int lane = threadIdx.x & 31;
    int v = blockIdx.x * 256 + (threadIdx.x >> 5) * 32 + lane;

    int   mylab = labels[v];                  // coalesced
    float myw   = wts[v];                     // coalesced
    int   mysh  = useShared ? (int)g_shared[v] : 1;

    unsigned shmask = __ballot_sync(0xffffffffu, mysh != 0);
    float accRow = 0.f;
    float accD = (mysh == 0) ? myw * myw : 0.f;

    while (shmask) {
        int idx[4]; int cnt = 0;
#pragma unroll
        for (int k = 0; k < 4; k++)
            if (shmask) { idx[k] = __ffs(shmask) - 1; shmask &= shmask - 1; cnt = k + 1; }
        float x[4], wv[4];
#pragma unroll
        for (int k = 0; k < 4; k++) if (k < cnt) {
            int lab = __shfl_sync(0xffffffffu, mylab, idx[k]);
            wv[k] = __shfl_sync(0xffffffffu, myw, idx[k]);
            x[k] = g_W[((size_t)(unsigned)lab << 5) + lane];
        }
#pragma unroll
        for (int k = 0; k < 4; k++) if (k < cnt)
            accRow = fmaf(wv[k], x[k], accRow);
    }

    // reduce: accRow -> K[g][lane], accD -> K[g][g]
#pragma unroll
    for (int o = 16; o; o >>= 1) accD += __shfl_xor_sync(0xffffffffu, accD, o);

    __shared__ float S[32];
    if (threadIdx.x < 32) S[threadIdx.x] = 0.f;
    __syncthreads();
    if (accRow != 0.f) atomicAdd(&S[lane], accRow);
    if (lane == 0 && accD != 0.f) atomicAdd(&S[g & 31], accD);
    __syncthreads();
    if (threadIdx.x < 32) {
        float val = S[threadIdx.x];
        if (val != 0.f) atomicAdd(&g_K[(g << 5) + threadIdx.x], val);
    }
}

// restore invariants: W own-cell, shared flags, hash table
__global__ void k_zero(const int* __restrict__ inputLab, int labSel, int doTable,
                       const int* nit, int iter) {
    if (iter > get_lim(nit)) return;
    int v = blockIdx.x * 256 + threadIdx.x;
    const int* labels = (labSel == 0) ? inputLab : (labSel == 1 ? g_labA : g_labB);
    int lab = labels[v];
    g_W[((size_t)(unsigned)lab << 5) + (v >> 13)] = 0.f;
    g_shared[v] = 0;
    if (doTable) {
        int4* tp = (int4*)g_table;            // 524288 int4 total, 2 per thread
        tp[v] = make_int4(0, 0, 0, 0);
        tp[v + CC] = make_int4(0, 0, 0, 0);
    }
}

__global__ void k_norm(float* __restrict__ out) {
    int t = threadIdx.x;  // 1024 threads
    int i = t >> 5, j = t & 31;
    float dij = sqrtf(g_K[i * 32 + i] * g_K[j * 32 + j]);
    out[t] = g_K[t] / dij;
}

// ---------------- host launcher ----------------
extern "C" void kernel_launch(void* const* d_in, const int* in_sizes, int n_in,
                              void* d_out, int out_size) {
    const int*   nbr = (const int*)d_in[0];
    const int*   il  = (const int*)d_in[1];
    const float* wts = (const float*)d_in[2];
    const int*   nit = (n_in >= 4) ? (const int*)d_in[3] : nullptr;
    float* out = (float*)d_out;

    k_init<<<CC / 256, 256>>>(il, wts);
    k_gramv<<<CC / 256, 256>>>(il, wts, 0, /*useShared=*/0, nit, 0);
    k_zero<<<CC / 256, 256>>>(il, 0, /*doTable=*/0, nit, 0);

    const int srcSel[3] = {0, 1, 2};
    const int dstSel[3] = {1, 2, 1};
    for (int it = 1; it <= 3; ++it) {
        k_relabel<<<(GG * NN) / 512, 512>>>(nbr, il, wts,
                                            srcSel[it - 1], dstSel[it - 1], nit, it);
        k_gramv<<<CC / 256, 256>>>(il, wts, dstSel[it - 1], /*useShared=*/1, nit, it);
        k_zero<<<CC / 256, 256>>>(il, dstSel[it - 1], /*doTable=*/1, nit, it);
    }
    k_norm<<<1, 1024>>>(out);
    (void)in_sizes; (void)out_size;
}

// round 6
// speedup vs baseline: 6.1855x; 1.0840x over previous
#include <cuda_runtime.h>
#include <cstdint>

#define GG 32          // graphs
#define NN 8192        // nodes per graph
#define DD 32          // neighbors per node
#define CC (GG * NN)   // 262144 total nodes == label space
#define TSZ (1 << 20)  // hash table slots

#define LABMASK 0x7FFFFull            // low 19 bits: node_id+1
#define TAGMASK (~0x7FFFFull)         // high 45 bits: hash tag

// ---------------- device scratch (all zero-invariant across calls) ----------------
__device__ unsigned long long g_table[TSZ];   // (tag)|(node+1), 0 = empty (8MB)
__device__ float g_W[(size_t)CC * GG];        // (label, graph) weights (32MB)
__device__ float g_K[GG * GG];
__device__ int   g_labA[CC];
__device__ int   g_labB[CC];
__device__ unsigned char g_shared[CC];        // 1 = node's class has >1 member
__device__ unsigned g_cnt0;                   // max init label + 1 (reset by k_gram0)

__device__ __forceinline__ int get_lim(const int* nit) { return nit ? *nit : 3; }

__device__ __forceinline__ unsigned mix32(unsigned x) {
    x ^= x >> 16; x *= 0x7feb352du;
    x ^= x >> 15; x *= 0x846ca68bu;
    x ^= x >> 16;
    return x;
}
__device__ __forceinline__ unsigned long long mix64(unsigned long long x) {
    x ^= x >> 30; x *= 0xbf58476d1ce4e5b9ULL;
    x ^= x >> 27; x *= 0x94d049bb133111ebULL;
    x ^= x >> 31;
    return x;
}

// ---------------- kernels ----------------

// init: per-block smem histogram of init labels into W, track label bound
__global__ void __launch_bounds__(256)
k_init(const int* __restrict__ il, const float* __restrict__ w) {
    __shared__ float hist[4096];
    int t = blockIdx.x * 256 + threadIdx.x;
    for (int i = threadIdx.x; i < 4096; i += 256) hist[i] = 0.f;
    __syncthreads();

    int l = il[t];
    float wv = w[t];

    unsigned m = (unsigned)(l + 1);
#pragma unroll
    for (int o = 16; o > 0; o >>= 1)
        m = max(m, __shfl_xor_sync(0xffffffffu, m, o));
    if ((threadIdx.x & 31) == 0) atomicMax(&g_cnt0, m);

    if ((unsigned)l < 4096u) atomicAdd(&hist[l], wv);
    else atomicAdd(&g_W[((size_t)(unsigned)l << 5) + (t >> 13)], wv);
    __syncthreads();

    int g = t >> 13;   // block covers 256 nodes of one graph
    for (int i = threadIdx.x; i < 4096; i += 256) {
        float v = hist[i];
        if (v != 0.f) atomicAdd(&g_W[((size_t)i << 5) + g], v);
    }
}

// iteration-0 Gram from the W histogram: K[i][j] = sum_l W[l][i]*W[l][j]
// over l < nlab; stages rows through smem, zeroes them, resets g_cnt0.
// One block, 1024 threads (thread t owns K cell (t>>5, t&31)).
__global__ void __launch_bounds__(1024)
k_gram0() {
    __shared__ float R[256 * 32];   // 32KB chunk of W rows
    int i = threadIdx.x >> 5, j = threadIdx.x & 31;
    int nlab = (int)g_cnt0;
    float acc = 0.f;
    for (int base = 0; base < nlab; base += 256) {
        int cnt = min(256, nlab - base);
        for (int idx = threadIdx.x; idx < cnt * 32; idx += 1024) {
            R[idx] = g_W[(size_t)base * 32 + idx];
            g_W[(size_t)base * 32 + idx] = 0.f;   // restore zero-invariant
        }
        __syncthreads();
        for (int l = 0; l < cnt; l++)
            acc = fmaf(R[l * 32 + i], R[l * 32 + j], acc);
        __syncthreads();
    }
    g_K[threadIdx.x] = acc;
    if (threadIdx.x == 0) g_cnt0 = 0u;            // restore invariant
}

// fused relabel + label-resolve + histogram + shared-class flagging.
// 32-bit wrapping multiset signature (sum, sum-of-squares) in 4 independent
// accumulator chains; 64-bit mixing only at the ends.
__global__ void __launch_bounds__(512)
k_relabel(const int* __restrict__ nbr, const int* __restrict__ inputLab,
          const float* __restrict__ wts, int srcSel, int dstSel,
          const int* nit, int iter) {
    if (iter > get_lim(nit)) return;
    __shared__ unsigned sm[NN];  // 32KB premixed labels of this graph
    int g = blockIdx.x >> 4;                // 16 blocks per graph
    int nbase = (blockIdx.x & 15) * 512;
    const int* prev = (srcSel == 0) ? inputLab : (srcSel == 1 ? g_labA : g_labB);
    const int* gl = prev + g * NN;
    {   // stage + premix via int4
        const int4* gl4 = (const int4*)gl;
        uint4* sm4 = (uint4*)sm;
#pragma unroll
        for (int q = 0; q < 4; q++) {
            int i = threadIdx.x + q * 512;
            int4 t = gl4[i];
            sm4[i] = make_uint4(mix32((unsigned)t.x), mix32((unsigned)t.y),
                                mix32((unsigned)t.z), mix32((unsigned)t.w));
        }
    }
    __syncthreads();

    int n = nbase + threadIdx.x;
    int node = g * NN + n;

    int4 tq[8];
    const int4* np = (const int4*)(nbr + (size_t)node * DD);
#pragma unroll
    for (int q = 0; q < 8; q++) tq[q] = np[q];

    float wv = wts[node];                   // hoist independent load

    unsigned s1a = 0u, s1b = 0u, s2a = 0u, s2b = 0u;
#pragma unroll
    for (int q = 0; q < 8; q++) {
        unsigned m0 = sm[tq[q].x], m1 = sm[tq[q].y], m2 = sm[tq[q].z], m3 = sm[tq[q].w];
        s1a += m0; s2a += m0 * m0;
        s1b += m1; s2b += m1 * m1;
        s1a += m2; s2a += m2 * m2;
        s1b += m3; s2b += m3 * m3;
    }
    unsigned s1 = s1a + s1b, s2 = s2a + s2b;

    unsigned long long A = mix64((unsigned long long)sm[n] ^ 0x9E3779B97F4A7C15ULL);
    unsigned long long h = mix64(A ^ (((unsigned long long)s1 << 32) | s2));
    unsigned long long cand = (h & TAGMASK) | (unsigned long long)(node + 1);
    unsigned s = (unsigned)h & (TSZ - 1);

    int lab;
    for (;;) {
        unsigned long long old = atomicCAS(&g_table[s], 0ull, cand);
        if (old == 0ull) { lab = node; break; }                  // winner: own id
        if (((old ^ cand) & TAGMASK) == 0ull) {                  // matched credential
            lab = (int)(old & LABMASK) - 1;                      // winner's id
            g_shared[node] = 1;
            g_shared[lab] = 1;
            break;
        }
        s = (s + 1) & (TSZ - 1);
    }

    if (dstSel == 1) g_labA[node] = lab; else g_labB[node] = lab;
    atomicAdd(&g_W[((size_t)(unsigned)lab << 5) + (unsigned)g], wv);
}

// per-node Gram with singleton fast path
__global__ void __launch_bounds__(256)
k_gramv(const float* __restrict__ wts, int labSel, const int* nit, int iter) {
    if (iter > get_lim(nit)) return;
    const int* labels = (labSel == 1) ? g_labA : g_labB;
    int g = blockIdx.x >> 5;                  // 32 blocks per graph
    int lane = threadIdx.x & 31;
    int v = blockIdx.x * 256 + (threadIdx.x >> 5) * 32 + lane;

    int   mylab = labels[v];
    float myw   = wts[v];
    int   mysh  = (int)g_shared[v];

    unsigned shmask = __ballot_sync(0xffffffffu, mysh != 0);
    float accRow = 0.f;
    float accD = (mysh == 0) ? myw * myw : 0.f;

    while (shmask) {
        int idx[4]; int cnt = 0;
#pragma unroll
        for (int k = 0; k < 4; k++)
            if (shmask) { idx[k] = __ffs(shmask) - 1; shmask &= shmask - 1; cnt = k + 1; }
        float x[4], wl[4];
#pragma unroll
        for (int k = 0; k < 4; k++) if (k < cnt) {
            int lab = __shfl_sync(0xffffffffu, mylab, idx[k]);
            wl[k] = __shfl_sync(0xffffffffu, myw, idx[k]);
            x[k] = g_W[((size_t)(unsigned)lab << 5) + lane];
        }
#pragma unroll
        for (int k = 0; k < 4; k++) if (k < cnt)
            accRow = fmaf(wl[k], x[k], accRow);
    }

#pragma unroll
    for (int o = 16; o; o >>= 1) accD += __shfl_xor_sync(0xffffffffu, accD, o);

    __shared__ float S[32];
    if (threadIdx.x < 32) S[threadIdx.x] = 0.f;
    __syncthreads();
    if (accRow != 0.f) atomicAdd(&S[lane], accRow);
    if (lane == 0 && accD != 0.f) atomicAdd(&S[g & 31], accD);
    __syncthreads();
    if (threadIdx.x < 32) {
        float val = S[threadIdx.x];
        if (val != 0.f) atomicAdd(&g_K[(g << 5) + threadIdx.x], val);
    }
}

// restore invariants: W own-cell, shared flags, hash table
__global__ void k_zero(int labSel, const int* nit, int iter) {
    if (iter > get_lim(nit)) return;
    int v = blockIdx.x * 256 + threadIdx.x;
    const int* labels = (labSel == 1) ? g_labA : g_labB;
    int lab = labels[v];
    g_W[((size_t)(unsigned)lab << 5) + (v >> 13)] = 0.f;
    g_shared[v] = 0;
    int4* tp = (int4*)g_table;                // 524288 int4 total, 2 per thread
    tp[v] = make_int4(0, 0, 0, 0);
    tp[v + CC] = make_int4(0, 0, 0, 0);
}

__global__ void k_norm(float* __restrict__ out) {
    int t = threadIdx.x;  // 1024 threads
    int i = t >> 5, j = t & 31;
    float dij = sqrtf(g_K[i * 32 + i] * g_K[j * 32 + j]);
    out[t] = g_K[t] / dij;
}

// ---------------- host launcher ----------------
extern "C" void kernel_launch(void* const* d_in, const int* in_sizes, int n_in,
                              void* d_out, int out_size) {
    const int*   nbr = (const int*)d_in[0];
    const int*   il  = (const int*)d_in[1];
    const float* wts = (const float*)d_in[2];
    const int*   nit = (n_in >= 4) ? (const int*)d_in[3] : nullptr;
    float* out = (float*)d_out;

    k_init<<<CC / 256, 256>>>(il, wts);
    k_gram0<<<1, 1024>>>();

    const int srcSel[3] = {0, 1, 2};
    const int dstSel[3] = {1, 2, 1};
    for (int it = 1; it <= 3; ++it) {
        k_relabel<<<(GG * NN) / 512, 512>>>(nbr, il, wts,
                                            srcSel[it - 1], dstSel[it - 1], nit, it);
        k_gramv<<<CC / 256, 256>>>(wts, dstSel[it - 1], nit, it);
        k_zero<<<CC / 256, 256>>>(dstSel[it - 1], nit, it);
    }
    k_norm<<<1, 1024>>>(out);
    (void)in_sizes; (void)out_size;
}

// round 7
// speedup vs baseline: 10.6920x; 1.7286x over previous
#include <cuda_runtime.h>
#include <cstdint>

#define GG 32          // graphs
#define NN 8192        // nodes per graph
#define DD 32          // neighbors per node
#define CC (GG * NN)   // 262144 total nodes == label space
#define TSZ (1 << 20)  // hash table slots

#define LABMASK 0x7FFFFull            // low 19 bits: node_id+1
#define TAGMASK (~0x7FFFFull)         // high 45 bits: hash tag

// ---------------- device scratch (zero-invariant across calls) ----------------
__device__ unsigned long long g_table[TSZ];   // (tag)|(node+1), 0 = empty (8MB)
__device__ float g_W[(size_t)CC * GG];        // (label, graph) weights (32MB)
__device__ float g_K[GG * GG];                // overwritten by k_gram0 each run
__device__ int   g_labA[CC];
__device__ int   g_labB[CC];
__device__ unsigned char g_F1[CC];            // shared-class flags (iters 1,3)
__device__ unsigned char g_F2[CC];            // shared-class flags (iter 2)
__device__ float g_Q[GG];                     // per-graph sum of w^2
__device__ unsigned g_cnt0;                   // max init label + 1

__device__ __forceinline__ int get_lim(const int* nit) {
    int l = nit ? *nit : 3;
    return l < 3 ? l : 3;
}

__device__ __forceinline__ unsigned mix32(unsigned x) {
    x ^= x >> 16; x *= 0x7feb352du;
    x ^= x >> 15; x *= 0x846ca68bu;
    x ^= x >> 16;
    return x;
}
__device__ __forceinline__ unsigned long long mix64(unsigned long long x) {
    x ^= x >> 30; x *= 0xbf58476d1ce4e5b9ULL;
    x ^= x >> 27; x *= 0x94d049bb133111ebULL;
    x ^= x >> 31;
    return x;
}

// ---------------- kernels ----------------

// init: smem histogram of init labels into W, Q[g] = sum w^2, label bound
__global__ void __launch_bounds__(256)
k_init(const int* __restrict__ il, const float* __restrict__ w) {
    __shared__ float hist[4096];
    __shared__ float red[8];
    int t = blockIdx.x * 256 + threadIdx.x;
    for (int i = threadIdx.x; i < 4096; i += 256) hist[i] = 0.f;
    __syncthreads();

    int l = il[t];
    float wv = w[t];
    int g = t >> 13;

    unsigned m = (unsigned)(l + 1);
#pragma unroll
    for (int o = 16; o > 0; o >>= 1)
        m = max(m, __shfl_xor_sync(0xffffffffu, m, o));
    if ((threadIdx.x & 31) == 0) atomicMax(&g_cnt0, m);

    float q = wv * wv;
#pragma unroll
    for (int o = 16; o > 0; o >>= 1)
        q += __shfl_xor_sync(0xffffffffu, q, o);
    if ((threadIdx.x & 31) == 0) red[threadIdx.x >> 5] = q;

    if ((unsigned)l < 4096u) atomicAdd(&hist[l], wv);
    else atomicAdd(&g_W[((size_t)(unsigned)l << 5) + g], wv);
    __syncthreads();

    if (threadIdx.x == 0) {
        float s = 0.f;
#pragma unroll
        for (int i = 0; i < 8; i++) s += red[i];
        atomicAdd(&g_Q[g], s);
    }
    for (int i = threadIdx.x; i < 4096; i += 256) {
        float v = hist[i];
        if (v != 0.f) atomicAdd(&g_W[((size_t)i << 5) + g], v);
    }
}

// iteration-0 Gram (overwrites K), zeroes the used W rows, resets g_cnt0
__global__ void __launch_bounds__(1024)
k_gram0() {
    __shared__ float R[256 * 32];
    int i = threadIdx.x >> 5, j = threadIdx.x & 31;
    int nlab = (int)g_cnt0;
    float acc = 0.f;
    for (int base = 0; base < nlab; base += 256) {
        int cnt = min(256, nlab - base);
        for (int idx = threadIdx.x; idx < cnt * 32; idx += 1024) {
            R[idx] = g_W[(size_t)base * 32 + idx];
            g_W[(size_t)base * 32 + idx] = 0.f;
        }
        __syncthreads();
        for (int l = 0; l < cnt; l++)
            acc = fmaf(R[l * 32 + i], R[l * 32 + j], acc);
        __syncthreads();
    }
    g_K[threadIdx.x] = acc;
    if (threadIdx.x == 0) g_cnt0 = 0u;
}

// relabel with singleton skip:
//   need = (no src flags) or flagged-shared last iteration.
//   skipped nodes: new label = old label (provably still singleton).
//   needed nodes: premixed smem gather, 32-bit (sum, sumsq) signature,
//   packed CAS table resolve, flag + W histogram writes.
__global__ void __launch_bounds__(512)
k_relabel(const int* __restrict__ nbr, const int* __restrict__ inputLab,
          const float* __restrict__ wts, int srcSel, int dstSel,
          int fsrcSel, int fdstSel, const int* nit, int iter) {
    if (iter > get_lim(nit)) return;
    __shared__ unsigned sm[NN];
    int g = blockIdx.x >> 4;
    int nbase = (blockIdx.x & 15) * 512;
    const int* prev = (srcSel == 0) ? inputLab : (srcSel == 1 ? g_labA : g_labB);
    const int* gl = prev + g * NN;
    int n = nbase + threadIdx.x;
    int node = g * NN + n;

    bool need;
    if (fsrcSel == 0) need = true;
    else {
        const unsigned char* fs = (fsrcSel == 1) ? g_F1 : g_F2;
        need = (fs[node] != 0);
    }

    int any = __syncthreads_or((int)need);
    if (any) {
        const int4* gl4 = (const int4*)gl;
        uint4* sm4 = (uint4*)sm;
#pragma unroll
        for (int q = 0; q < 4; q++) {
            int i = threadIdx.x + q * 512;
            int4 t = gl4[i];
            sm4[i] = make_uint4(mix32((unsigned)t.x), mix32((unsigned)t.y),
                                mix32((unsigned)t.z), mix32((unsigned)t.w));
        }
        __syncthreads();
    }

    int lab;
    if (need) {
        int4 tq[8];
        const int4* np = (const int4*)(nbr + (size_t)node * DD);
#pragma unroll
        for (int q = 0; q < 8; q++) tq[q] = np[q];
        float wv = wts[node];

        unsigned s1a = 0u, s1b = 0u, s2a = 0u, s2b = 0u;
#pragma unroll
        for (int q = 0; q < 8; q++) {
            unsigned m0 = sm[tq[q].x], m1 = sm[tq[q].y], m2 = sm[tq[q].z], m3 = sm[tq[q].w];
            s1a += m0; s2a += m0 * m0;
            s1b += m1; s2b += m1 * m1;
            s1a += m2; s2a += m2 * m2;
            s1b += m3; s2b += m3 * m3;
        }
        unsigned s1 = s1a + s1b, s2 = s2a + s2b;

        unsigned long long A = mix64((unsigned long long)sm[n] ^ 0x9E3779B97F4A7C15ULL);
        unsigned long long h = mix64(A ^ (((unsigned long long)s1 << 32) | s2));
        unsigned long long cand = (h & TAGMASK) | (unsigned long long)(node + 1);
        unsigned s = (unsigned)h & (TSZ - 1);

        unsigned char* fd = (fdstSel == 1) ? g_F1 : g_F2;
        for (;;) {
            unsigned long long old = atomicCAS(&g_table[s], 0ull, cand);
            if (old == 0ull) { lab = node; break; }
            if (((old ^ cand) & TAGMASK) == 0ull) {
                lab = (int)(old & LABMASK) - 1;
                fd[node] = 1;
                fd[lab] = 1;
                break;
            }
            s = (s + 1) & (TSZ - 1);
        }
        atomicAdd(&g_W[((size_t)(unsigned)lab << 5) + (unsigned)g], wv);
    } else {
        lab = gl[n];   // singleton: label persists
    }

    if (dstSel == 1) g_labA[node] = lab; else g_labB[node] = lab;
}

// Gram over FLAGGED nodes only (singleton diagonal handled by Q in k_norm):
//   K[g][:] += w * W[lab][:]  for flagged v;  K[g][g] -= w^2 for flagged v.
__global__ void __launch_bounds__(256)
k_gramv(const float* __restrict__ wts, int labSel, int fSel,
        const int* nit, int iter) {
    if (iter > get_lim(nit)) return;
    int v = blockIdx.x * 256 + threadIdx.x;
    const unsigned char* f = (fSel == 1) ? g_F1 : g_F2;
    bool flagged = (f[v] != 0);
    if (!__syncthreads_or((int)flagged)) return;   // common case: whole block clean

    const int* labels = (labSel == 1) ? g_labA : g_labB;
    int g = blockIdx.x >> 5;
    int lane = threadIdx.x & 31;

    unsigned shmask = __ballot_sync(0xffffffffu, flagged);
    float accRow = 0.f, accSub = 0.f;
    int mylab = 0; float myw = 0.f;
    if (shmask) { mylab = labels[v]; myw = wts[v]; }
    if (flagged) accSub = myw * myw;

    while (shmask) {
        int idx[4]; int cnt = 0;
#pragma unroll
        for (int k = 0; k < 4; k++)
            if (shmask) { idx[k] = __ffs(shmask) - 1; shmask &= shmask - 1; cnt = k + 1; }
        float x[4], wl[4];
#pragma unroll
        for (int k = 0; k < 4; k++) if (k < cnt) {
            int lab = __shfl_sync(0xffffffffu, mylab, idx[k]);
            wl[k] = __shfl_sync(0xffffffffu, myw, idx[k]);
            x[k] = g_W[((size_t)(unsigned)lab << 5) + lane];
        }
#pragma unroll
        for (int k = 0; k < 4; k++) if (k < cnt)
            accRow = fmaf(wl[k], x[k], accRow);
    }

#pragma unroll
    for (int o = 16; o; o >>= 1) accSub += __shfl_xor_sync(0xffffffffu, accSub, o);

    __shared__ float S[32];
    if (threadIdx.x < 32) S[threadIdx.x] = 0.f;
    __syncthreads();
    if (accRow != 0.f) atomicAdd(&S[lane], accRow);
    if (lane == 0 && accSub != 0.f) atomicAdd(&S[g & 31], -accSub);
    __syncthreads();
    if (threadIdx.x < 32) {
        float val = S[threadIdx.x];
        if (val != 0.f) atomicAdd(&g_K[(g << 5) + threadIdx.x], val);
    }
}

// restore invariants: W cells (predicated), hash table, flag arrays per schedule
__global__ void k_zero(int labSel, int predSel, const int* nit, int iter) {
    int lim = get_lim(nit);
    if (iter > lim) return;
    int v = blockIdx.x * 256 + threadIdx.x;
    const int* labels = (labSel == 1) ? g_labA : g_labB;

    bool doW;
    if (predSel == 0) doW = true;
    else doW = ((predSel == 1 ? g_F1[v] : g_F2[v]) != 0);
    if (doW) g_W[((size_t)(unsigned)labels[v] << 5) + (v >> 13)] = 0.f;

    if (iter == 1) { if (lim == 1) g_F1[v] = 0; }
    else if (iter == 2) { g_F1[v] = 0; if (lim == 2) g_F2[v] = 0; }
    else { g_F1[v] = 0; g_F2[v] = 0; }

    int4* tp = (int4*)g_table;
    tp[v] = make_int4(0, 0, 0, 0);
    tp[v + CC] = make_int4(0, 0, 0, 0);
}

// normalize; fold in the singleton diagonal lim*Q; clear Q
__global__ void k_norm(float* __restrict__ out, const int* nit) {
    int t = threadIdx.x;  // 1024 threads
    int i = t >> 5, j = t & 31;
    int lim = get_lim(nit);
    __shared__ float d[32];
    float kij = g_K[t] + ((i == j) ? (float)lim * g_Q[i] : 0.f);
    if (i == j) d[i] = kij;
    __syncthreads();
    out[t] = kij / sqrtf(d[i] * d[j]);
    if (t < 32) g_Q[t] = 0.f;
}

// ---------------- host launcher ----------------
extern "C" void kernel_launch(void* const* d_in, const int* in_sizes, int n_in,
                              void* d_out, int out_size) {
    const int*   nbr = (const int*)d_in[0];
    const int*   il  = (const int*)d_in[1];
    const float* wts = (const float*)d_in[2];
    const int*   nit = (n_in >= 4) ? (const int*)d_in[3] : nullptr;
    float* out = (float*)d_out;

    k_init<<<CC / 256, 256>>>(il, wts);
    k_gram0<<<1, 1024>>>();

    //                 it1        it2        it3
    const int srcSel [3] = {0, 1, 2};    // labels: input, A, B
    const int dstSel [3] = {1, 2, 1};    // labels: A, B, A
    const int fsrcSel[3] = {0, 1, 2};    // flags:  none, F1, F2
    const int fdstSel[3] = {1, 2, 1};    // flags:  F1, F2, F1
    for (int it = 1; it <= 3; ++it) {
        k_relabel<<<(GG * NN) / 512, 512>>>(nbr, il, wts,
                                            srcSel[it - 1], dstSel[it - 1],
                                            fsrcSel[it - 1], fdstSel[it - 1],
                                            nit, it);
        k_gramv<<<CC / 256, 256>>>(wts, dstSel[it - 1], fdstSel[it - 1], nit, it);
        k_zero<<<CC / 256, 256>>>(dstSel[it - 1], fsrcSel[it - 1], nit, it);
    }
    k_norm<<<1, 1024>>>(out, nit);
    (void)in_sizes; (void)out_size;
}

// round 8
// speedup vs baseline: 11.1309x; 1.0410x over previous
#include <cuda_runtime.h>
#include <cstdint>

#define GG 32          // graphs
#define NN 8192        // nodes per graph
#define DD 32          // neighbors per node
#define CC (GG * NN)   // 262144 total nodes == label space
#define TSZ (1 << 20)  // hash table slots

#define LABMASK 0x7FFFFull            // low 19 bits: node_id+1
#define TAGMASK (~0x7FFFFull)         // high 45 bits: hash tag

// ---------------- device scratch ----------------
__device__ unsigned long long g_table[TSZ];   // (tag)|(node+1), 0 = empty (8MB); zero-invariant
__device__ float g_W[(size_t)CC * GG];        // (label, graph) weights (32MB); zero-invariant
__device__ float g_K[GG * GG];                // overwritten each run
__device__ int   g_labA[CC];
__device__ int   g_labB[CC];
__device__ int   g_F1i[CC];                   // shared flags (iters 1,3); zero-invariant
__device__ int   g_F2i[CC];                   // shared flags (iter 2);    zero-invariant
__device__ int   g_L1[CC];                    // flagged-node lists (contents gated by counters)
__device__ int   g_L2[CC];
__device__ int   g_S[CC];                     // winner slot list (iters 2,3)
__device__ unsigned g_nL[4];                  // per-iter list counts (reset in k_init)
__device__ unsigned g_nS[4];
__device__ float g_Q[GG];                     // per-graph sum of w^2; cleared in k_norm
__device__ unsigned g_cnt0;                   // max init label + 1; reset in k_gram0

__device__ __forceinline__ int get_lim(const int* nit) {
    int l = nit ? *nit : 3;
    return l < 3 ? l : 3;
}

__device__ __forceinline__ unsigned mix32(unsigned x) {
    x ^= x >> 16; x *= 0x7feb352du;
    x ^= x >> 15; x *= 0x846ca68bu;
    x ^= x >> 16;
    return x;
}
__device__ __forceinline__ unsigned long long mix64(unsigned long long x) {
    x ^= x >> 30; x *= 0xbf58476d1ce4e5b9ULL;
    x ^= x >> 27; x *= 0x94d049bb133111ebULL;
    x ^= x >> 31;
    return x;
}

// ---------------- kernels ----------------

// init: smem histogram of init labels into W, Q[g] = sum w^2, label bound,
// reset per-iter list counters
__global__ void __launch_bounds__(256)
k_init(const int* __restrict__ il, const float* __restrict__ w) {
    __shared__ float hist[4096];
    __shared__ float red[8];
    int t = blockIdx.x * 256 + threadIdx.x;
    for (int i = threadIdx.x; i < 4096; i += 256) hist[i] = 0.f;
    if (t == 0) {
#pragma unroll
        for (int i = 0; i < 4; i++) { g_nL[i] = 0u; g_nS[i] = 0u; }
    }
    __syncthreads();

    int l = il[t];
    float wv = w[t];
    int g = t >> 13;

    unsigned m = (unsigned)(l + 1);
#pragma unroll
    for (int o = 16; o > 0; o >>= 1)
        m = max(m, __shfl_xor_sync(0xffffffffu, m, o));
    if ((threadIdx.x & 31) == 0) atomicMax(&g_cnt0, m);

    float q = wv * wv;
#pragma unroll
    for (int o = 16; o > 0; o >>= 1)
        q += __shfl_xor_sync(0xffffffffu, q, o);
    if ((threadIdx.x & 31) == 0) red[threadIdx.x >> 5] = q;

    if ((unsigned)l < 4096u) atomicAdd(&hist[l], wv);
    else atomicAdd(&g_W[((size_t)(unsigned)l << 5) + g], wv);
    __syncthreads();

    if (threadIdx.x == 0) {
        float s = 0.f;
#pragma unroll
        for (int i = 0; i < 8; i++) s += red[i];
        atomicAdd(&g_Q[g], s);
    }
    for (int i = threadIdx.x; i < 4096; i += 256) {
        float v = hist[i];
        if (v != 0.f) atomicAdd(&g_W[((size_t)i << 5) + g], v);
    }
}

// iteration-0 Gram (overwrites K), zeroes the used W rows, resets g_cnt0
__global__ void __launch_bounds__(1024)
k_gram0() {
    __shared__ float R[256 * 32];
    int i = threadIdx.x >> 5, j = threadIdx.x & 31;
    int nlab = (int)g_cnt0;
    float acc = 0.f;
    for (int base = 0; base < nlab; base += 256) {
        int cnt = min(256, nlab - base);
        for (int idx = threadIdx.x; idx < cnt * 32; idx += 1024) {
            R[idx] = g_W[(size_t)base * 32 + idx];
            g_W[(size_t)base * 32 + idx] = 0.f;
        }
        __syncthreads();
        for (int l = 0; l < cnt; l++)
            acc = fmaf(R[l * 32 + i], R[l * 32 + j], acc);
        __syncthreads();
    }
    g_K[threadIdx.x] = acc;
    if (threadIdx.x == 0) g_cnt0 = 0u;
}

// relabel with singleton skip + deferred W + worklist appends.
//   need = no-src-flags OR flagged last iter (flag consumed: cleared on read).
//   losers: flag self, append self (warp-aggregated); flag+append winner (deduped).
//   winners (iters>=2): append claimed slot for targeted table clearing.
__global__ void __launch_bounds__(512)
k_relabel(const int* __restrict__ nbr, const int* __restrict__ inputLab,
          int srcSel, int dstSel, int fsrcSel, int fdstSel,
          int listSel, int appendSlots, const int* nit, int iter) {
    if (iter > get_lim(nit)) return;
    __shared__ unsigned sm[NN];
    int g = blockIdx.x >> 4;
    int nbase = (blockIdx.x & 15) * 512;
    const int* prev = (srcSel == 0) ? inputLab : (srcSel == 1 ? g_labA : g_labB);
    const int* gl = prev + g * NN;
    int n = nbase + threadIdx.x;
    int node = g * NN + n;

    bool need;
    if (fsrcSel == 0) need = true;
    else {
        int* fs = (fsrcSel == 1) ? g_F1i : g_F2i;
        need = (fs[node] != 0);
        if (need) fs[node] = 0;          // consume flag
    }

    int any = __syncthreads_or((int)need);
    if (any) {
        const int4* gl4 = (const int4*)gl;
        uint4* sm4 = (uint4*)sm;
#pragma unroll
        for (int q = 0; q < 4; q++) {
            int i = threadIdx.x + q * 512;
            int4 t = gl4[i];
            sm4[i] = make_uint4(mix32((unsigned)t.x), mix32((unsigned)t.y),
                                mix32((unsigned)t.z), mix32((unsigned)t.w));
        }
        __syncthreads();
    }

    int lab;
    bool isLoser = false, isWinner = false;
    unsigned slot = 0;
    int* fd = (fdstSel == 1) ? g_F1i : g_F2i;
    int* Ld = (listSel == 1) ? g_L1 : g_L2;

    if (need) {
        int4 tq[8];
        const int4* np = (const int4*)(nbr + (size_t)node * DD);
#pragma unroll
        for (int q = 0; q < 8; q++) tq[q] = np[q];

        unsigned s1a = 0u, s1b = 0u, s2a = 0u, s2b = 0u;
#pragma unroll
        for (int q = 0; q < 8; q++) {
            unsigned m0 = sm[tq[q].x], m1 = sm[tq[q].y], m2 = sm[tq[q].z], m3 = sm[tq[q].w];
            s1a += m0; s2a += m0 * m0;
            s1b += m1; s2b += m1 * m1;
            s1a += m2; s2a += m2 * m2;
            s1b += m3; s2b += m3 * m3;
        }
        unsigned s1 = s1a + s1b, s2 = s2a + s2b;

        unsigned long long A = mix64((unsigned long long)sm[n] ^ 0x9E3779B97F4A7C15ULL);
        unsigned long long h = mix64(A ^ (((unsigned long long)s1 << 32) | s2));
        unsigned long long cand = (h & TAGMASK) | (unsigned long long)(node + 1);
        unsigned s = (unsigned)h & (TSZ - 1);

        for (;;) {
            unsigned long long old = atomicCAS(&g_table[s], 0ull, cand);
            if (old == 0ull) { lab = node; isWinner = true; slot = s; break; }
            if (((old ^ cand) & TAGMASK) == 0ull) {
                lab = (int)(old & LABMASK) - 1;       // winner's id
                isLoser = true;
                fd[node] = 1;                          // flag self
                if (atomicExch(&fd[lab], 1) == 0) {    // flag + append winner once
                    unsigned p = atomicAdd(&g_nL[iter], 1u);
                    Ld[p] = lab;
                }
                break;
            }
            s = (s + 1) & (TSZ - 1);
        }
    } else {
        lab = gl[n];   // singleton persists
    }

    // warp-aggregated self-append of losers
    unsigned lm = __ballot_sync(0xffffffffu, isLoser);
    if (lm) {
        int lane = threadIdx.x & 31;
        int leader = __ffs(lm) - 1;
        unsigned base = 0;
        if (lane == leader) base = atomicAdd(&g_nL[iter], (unsigned)__popc(lm));
        base = __shfl_sync(0xffffffffu, base, leader);
        if (isLoser) Ld[base + __popc(lm & ((1u << lane) - 1u))] = node;
    }
    // warp-aggregated slot appends (winners, iters >= 2)
    if (appendSlots) {
        unsigned wm = __ballot_sync(0xffffffffu, isWinner);
        if (wm) {
            int lane = threadIdx.x & 31;
            int leader = __ffs(wm) - 1;
            unsigned base = 0;
            if (lane == leader) base = atomicAdd(&g_nS[iter], (unsigned)__popc(wm));
            base = __shfl_sync(0xffffffffu, base, leader);
            if (isWinner) g_S[base + __popc(wm & ((1u << lane) - 1u))] = (int)slot;
        }
    }

    if (dstSel == 1) g_labA[node] = lab; else g_labB[node] = lab;
}

// W histogram over the flagged list only
__global__ void __launch_bounds__(256)
k_whist(const float* __restrict__ wts, int labSel, int listSel,
        const int* nit, int iter) {
    if (iter > get_lim(nit)) return;
    unsigned nn = g_nL[iter];
    if (nn == 0) return;
    const int* L = (listSel == 1) ? g_L1 : g_L2;
    const int* labels = (labSel == 1) ? g_labA : g_labB;
    for (unsigned i = blockIdx.x * 256 + threadIdx.x; i < nn; i += gridDim.x * 256) {
        int node = L[i];
        atomicAdd(&g_W[((size_t)(unsigned)labels[node] << 5) + (node >> 13)], wts[node]);
    }
}

// Gram over the flagged list: K[g][:] += w*W[lab][:], K[g][g] -= w^2
__global__ void __launch_bounds__(256)
k_gramvL(const float* __restrict__ wts, int labSel, int listSel,
         const int* nit, int iter) {
    if (iter > get_lim(nit)) return;
    unsigned nn = g_nL[iter];
    if (nn == 0) return;
    const int* L = (listSel == 1) ? g_L1 : g_L2;
    const int* labels = (labSel == 1) ? g_labA : g_labB;

    __shared__ float S[1024];
    for (int i = threadIdx.x; i < 1024; i += 256) S[i] = 0.f;
    __syncthreads();

    int lane = threadIdx.x & 31;
    unsigned gwarp = (blockIdx.x * 256 + threadIdx.x) >> 5;
    unsigned totW = (gridDim.x * 256) >> 5;

    for (unsigned base = gwarp * 32u; base < nn; base += totW * 32u) {
        unsigned idx = base + lane;
        int lab = 0, gg = 0; float w = 0.f;
        bool valid = (idx < nn);
        if (valid) {
            int node = L[idx];
            lab = labels[node]; w = wts[node]; gg = node >> 13;
        }
        int cnt = __popc(__ballot_sync(0xffffffffu, valid));  // valid lanes contiguous
        for (int k0 = 0; k0 < cnt; k0 += 4) {
            float x[4], wk[4]; int gk[4];
#pragma unroll
            for (int k = 0; k < 4; k++) if (k0 + k < cnt) {
                int lb = __shfl_sync(0xffffffffu, lab, k0 + k);
                wk[k] = __shfl_sync(0xffffffffu, w, k0 + k);
                gk[k] = __shfl_sync(0xffffffffu, gg, k0 + k);
                x[k] = g_W[((size_t)(unsigned)lb << 5) + lane];
            }
#pragma unroll
            for (int k = 0; k < 4; k++) if (k0 + k < cnt) {
                float val = wk[k] * x[k];
                if (lane == gk[k]) val -= wk[k] * wk[k];
                atomicAdd(&S[(gk[k] << 5) + lane], val);
            }
        }
    }
    __syncthreads();
    for (int i = threadIdx.x; i < 1024; i += 256) {
        float v = S[i];
        if (v != 0.f) atomicAdd(&g_K[i], v);
    }
}

// iter-1 cleanup: stream-clear hash table + list-driven W clears (+F1 if lim==1)
__global__ void __launch_bounds__(256)
k_zero1(const int* nit) {
    int lim = get_lim(nit);
    if (1 > lim) return;
    int v = blockIdx.x * 256 + threadIdx.x;   // grid 1024
    int4* tp = (int4*)g_table;
    tp[v] = make_int4(0, 0, 0, 0);
    tp[v + CC] = make_int4(0, 0, 0, 0);
    unsigned nn = g_nL[1];
    for (unsigned i = v; i < nn; i += 1024u * 256u) {
        int node = g_L1[i];
        g_W[((size_t)(unsigned)g_labA[node] << 5) + (node >> 13)] = 0.f;
        if (lim == 1) g_F1i[node] = 0;
    }
}

// iters 2,3 cleanup: list-driven W clears, slot-driven table clears,
// flag clears when this is the final iteration
__global__ void __launch_bounds__(256)
k_zeroL(int labSel, int listSel, int fSel, const int* nit, int iter) {
    int lim = get_lim(nit);
    if (iter > lim) return;
    unsigned nn = g_nL[iter];
    unsigned ns = g_nS[iter];
    const int* L = (listSel == 1) ? g_L1 : g_L2;
    const int* labels = (labSel == 1) ? g_labA : g_labB;
    int* f = (fSel == 1) ? g_F1i : g_F2i;
    unsigned t = blockIdx.x * 256 + threadIdx.x;
    unsigned stride = gridDim.x * 256;
    for (unsigned i = t; i < nn; i += stride) {
        int node = L[i];
        g_W[((size_t)(unsigned)labels[node] << 5) + (node >> 13)] = 0.f;
        if (iter == lim) f[node] = 0;
    }
    for (unsigned i = t; i < ns; i += stride)
        g_table[(unsigned)g_S[i]] = 0ull;
}

// normalize; fold in singleton diagonal lim*Q; clear Q
__global__ void k_norm(float* __restrict__ out, const int* nit) {
    int t = threadIdx.x;  // 1024 threads
    int i = t >> 5, j = t & 31;
    int lim = get_lim(nit);
    __shared__ float d[32];
    float kij = g_K[t] + ((i == j) ? (float)lim * g_Q[i] : 0.f);
    if (i == j) d[i] = kij;
    __syncthreads();
    out[t] = kij / sqrtf(d[i] * d[j]);
    if (t < 32) g_Q[t] = 0.f;
}

// ---------------- host launcher ----------------
extern "C" void kernel_launch(void* const* d_in, const int* in_sizes, int n_in,
                              void* d_out, int out_size) {
    const int*   nbr = (const int*)d_in[0];
    const int*   il  = (const int*)d_in[1];
    const float* wts = (const float*)d_in[2];
    const int*   nit = (n_in >= 4) ? (const int*)d_in[3] : nullptr;
    float* out = (float*)d_out;

    k_init<<<CC / 256, 256>>>(il, wts);
    k_gram0<<<1, 1024>>>();

    // iter 1: src=input, dst=A, flags -> F1, list -> L1, no slot appends
    k_relabel<<<512, 512>>>(nbr, il, 0, 1, 0, 1, 1, 0, nit, 1);
    k_whist  <<<64, 256>>>(wts, 1, 1, nit, 1);
    k_gramvL <<<64, 256>>>(wts, 1, 1, nit, 1);
    k_zero1  <<<1024, 256>>>(nit);

    // iter 2: src=A, dst=B, flags F1 -> F2, list -> L2, slots -> S
    k_relabel<<<512, 512>>>(nbr, il, 1, 2, 1, 2, 2, 1, nit, 2);
    k_whist  <<<64, 256>>>(wts, 2, 2, nit, 2);
    k_gramvL <<<64, 256>>>(wts, 2, 2, nit, 2);
    k_zeroL  <<<64, 256>>>(2, 2, 2, nit, 2);

    // iter 3: src=B, dst=A, flags F2 -> F1, list -> L1, slots -> S
    k_relabel<<<512, 512>>>(nbr, il, 2, 1, 2, 1, 1, 1, nit, 3);
    k_whist  <<<64, 256>>>(wts, 1, 1, nit, 3);
    k_gramvL <<<64, 256>>>(wts, 1, 1, nit, 3);
    k_zeroL  <<<64, 256>>>(1, 1, 1, nit, 3);

    k_norm<<<1, 1024>>>(out, nit);
    (void)in_sizes; (void)out_size;
}

// round 9
// speedup vs baseline: 13.0663x; 1.1739x over previous
#include <cuda_runtime.h>
#include <cstdint>

#define GG 32          // graphs
#define NN 8192        // nodes per graph
#define DD 32          // neighbors per node
#define CC (GG * NN)   // 262144 total nodes == label space
#define TSZ (1 << 20)  // hash table slots

#define LABMASK 0x7FFFFull            // low 19 bits: node_id+1
#define TAGMASK (~0x7FFFFull)         // high 45 bits: hash tag

// ---------------- device scratch ----------------
__device__ unsigned long long g_table[TSZ];   // (tag)|(node+1), 0 = empty; zero-invariant
__device__ float g_W[(size_t)CC * GG];        // (label, graph) weights (32MB); zero-invariant
__device__ float g_K[GG * GG];                // overwritten each run
__device__ int   g_labA[CC];
__device__ int   g_labB[CC];
__device__ int   g_F1i[CC];                   // shared flags (iters 1,3); zero-invariant
__device__ int   g_F2i[CC];                   // shared flags (iter 2);    zero-invariant
__device__ int   g_L1[CC];                    // flagged-node lists (gated by counters)
__device__ int   g_L2[CC];
__device__ unsigned g_nL[4];                  // per-iter list counts (reset in k_init)
__device__ float g_Q[GG];                     // per-graph sum of w^2; cleared in k_clearnorm
__device__ unsigned g_cnt0;                   // max init label + 1; reset in k_gram0

__device__ __forceinline__ int get_lim(const int* nit) {
    int l = nit ? *nit : 3;
    return l < 3 ? l : 3;
}

__device__ __forceinline__ unsigned mix32(unsigned x) {
    x ^= x >> 16; x *= 0x7feb352du;
    x ^= x >> 15; x *= 0x846ca68bu;
    x ^= x >> 16;
    return x;
}
__device__ __forceinline__ unsigned long long mix64(unsigned long long x) {
    x ^= x >> 30; x *= 0xbf58476d1ce4e5b9ULL;
    x ^= x >> 27; x *= 0x94d049bb133111ebULL;
    x ^= x >> 31;
    return x;
}

// ---------------- kernels ----------------

// init: smem histogram of init labels into W, Q[g] = sum w^2, label bound, counters
__global__ void __launch_bounds__(256)
k_init(const int* __restrict__ il, const float* __restrict__ w) {
    __shared__ float hist[4096];
    __shared__ float red[8];
    int t = blockIdx.x * 256 + threadIdx.x;
    for (int i = threadIdx.x; i < 4096; i += 256) hist[i] = 0.f;
    if (t == 0) {
#pragma unroll
        for (int i = 0; i < 4; i++) g_nL[i] = 0u;
    }
    __syncthreads();

    int l = il[t];
    float wv = w[t];
    int g = t >> 13;

    unsigned m = (unsigned)(l + 1);
#pragma unroll
    for (int o = 16; o > 0; o >>= 1)
        m = max(m, __shfl_xor_sync(0xffffffffu, m, o));
    if ((threadIdx.x & 31) == 0) atomicMax(&g_cnt0, m);

    float q = wv * wv;
#pragma unroll
    for (int o = 16; o > 0; o >>= 1)
        q += __shfl_xor_sync(0xffffffffu, q, o);
    if ((threadIdx.x & 31) == 0) red[threadIdx.x >> 5] = q;

    if ((unsigned)l < 4096u) atomicAdd(&hist[l], wv);
    else atomicAdd(&g_W[((size_t)(unsigned)l << 5) + g], wv);
    __syncthreads();

    if (threadIdx.x == 0) {
        float s = 0.f;
#pragma unroll
        for (int i = 0; i < 8; i++) s += red[i];
        atomicAdd(&g_Q[g], s);
    }
    for (int i = threadIdx.x; i < 4096; i += 256) {
        float v = hist[i];
        if (v != 0.f) atomicAdd(&g_W[((size_t)i << 5) + g], v);
    }
}

// iteration-0 Gram (overwrites K), zeroes used W rows, resets g_cnt0
__global__ void __launch_bounds__(1024)
k_gram0() {
    __shared__ float R[256 * 32];
    int i = threadIdx.x >> 5, j = threadIdx.x & 31;
    int nlab = (int)g_cnt0;
    float acc = 0.f;
    for (int base = 0; base < nlab; base += 256) {
        int cnt = min(256, nlab - base);
        for (int idx = threadIdx.x; idx < cnt * 32; idx += 1024) {
            R[idx] = g_W[(size_t)base * 32 + idx];
            g_W[(size_t)base * 32 + idx] = 0.f;
        }
        __syncthreads();
        for (int l = 0; l < cnt; l++)
            acc = fmaf(R[l * 32 + i], R[l * 32 + j], acc);
        __syncthreads();
    }
    g_K[threadIdx.x] = acc;
    if (threadIdx.x == 0) g_cnt0 = 0u;
}

// relabel: singleton skip; 4 threads per node (coalesced 32B loads, shfl-reduced
// signature); epoch-tagged hash table (no inter-iteration clears needed).
__global__ void __launch_bounds__(512)
k_relabel(const int* __restrict__ nbr, const int* __restrict__ inputLab,
          int srcSel, int dstSel, int fsrcSel, int fdstSel,
          int listSel, const int* nit, int iter) {
    if (iter > get_lim(nit)) return;
    __shared__ unsigned sm[NN];        // premixed labels of this graph
    __shared__ unsigned needMask[16];  // 512 need bits
    int g = blockIdx.x >> 4;
    int nbase = (blockIdx.x & 15) * 512;
    const int* prev = (srcSel == 0) ? inputLab : (srcSel == 1 ? g_labA : g_labB);
    const int* gl = prev + g * NN;
    int* dl = (dstSel == 1) ? g_labA : g_labB;
    int tid = threadIdx.x;

    // 1:1 need check, flag consume, singleton label copy
    int node0 = g * NN + nbase + tid;
    bool need;
    if (fsrcSel == 0) need = true;
    else {
        int* fs = (fsrcSel == 1) ? g_F1i : g_F2i;
        need = (fs[node0] != 0);
        if (need) fs[node0] = 0;
    }
    unsigned bm = __ballot_sync(0xffffffffu, need);
    if ((tid & 31) == 0) needMask[tid >> 5] = bm;
    if (!need) dl[node0] = gl[nbase + tid];   // singleton persists
    if (!__syncthreads_or((int)need)) return;

    // stage + premix labels
    {
        const int4* gl4 = (const int4*)gl;
        uint4* sm4 = (uint4*)sm;
#pragma unroll
        for (int q = 0; q < 4; q++) {
            int i = tid + q * 512;
            int4 t = gl4[i];
            sm4[i] = make_uint4(mix32((unsigned)t.x), mix32((unsigned)t.y),
                                mix32((unsigned)t.z), mix32((unsigned)t.w));
        }
        __syncthreads();
    }

    int* fd = (fdstSel == 1) ? g_F1i : g_F2i;
    int* Ld = (listSel == 1) ? g_L1 : g_L2;
    unsigned long long iterSalt = 0x9E3779B97F4A7C15ULL +
                                  (unsigned long long)iter * 0xA24BAED4963EE407ULL;
    int sub = tid >> 2;   // 0..127: node within pass
    int p = tid & 3;      // quarter

#pragma unroll
    for (int pass = 0; pass < 4; pass++) {
        int li = pass * 128 + sub;            // 0..511 within block
        int nodeLocal = nbase + li;
        int node = g * NN + nodeLocal;
        bool nd = (needMask[li >> 5] >> (li & 31)) & 1u;

        unsigned s1 = 0u, s2 = 0u;
        if (nd) {
            const int4* np = (const int4*)(nbr + (size_t)node * DD) + p * 2;
            int4 a = np[0], b = np[1];        // 32B contiguous per thread
            unsigned m;
            m = sm[a.x]; s1 += m; s2 += m * m;
            m = sm[a.y]; s1 += m; s2 += m * m;
            m = sm[a.z]; s1 += m; s2 += m * m;
            m = sm[a.w]; s1 += m; s2 += m * m;
            m = sm[b.x]; s1 += m; s2 += m * m;
            m = sm[b.y]; s1 += m; s2 += m * m;
            m = sm[b.z]; s1 += m; s2 += m * m;
            m = sm[b.w]; s1 += m; s2 += m * m;
        }
        // reduce over the 4 lanes of this node
        s1 += __shfl_xor_sync(0xffffffffu, s1, 1);
        s1 += __shfl_xor_sync(0xffffffffu, s1, 2);
        s2 += __shfl_xor_sync(0xffffffffu, s2, 1);
        s2 += __shfl_xor_sync(0xffffffffu, s2, 2);

        bool isLoser = false;
        int lab = 0;
        if (nd && p == 0) {
            unsigned long long A = mix64((unsigned long long)sm[nodeLocal] ^ iterSalt);
            unsigned long long h = mix64(A ^ (((unsigned long long)s1 << 32) | s2));
            unsigned long long cand = (h & TAGMASK) | (unsigned long long)(node + 1);
            unsigned s = (unsigned)h & (TSZ - 1);
            for (;;) {
                unsigned long long old = atomicCAS(&g_table[s], 0ull, cand);
                if (old == 0ull) { lab = node; break; }
                if (((old ^ cand) & TAGMASK) == 0ull) {
                    lab = (int)(old & LABMASK) - 1;
                    isLoser = true;
                    fd[node] = 1;
                    if (atomicExch(&fd[lab], 1) == 0) {    // flag + append winner once
                        unsigned pos = atomicAdd(&g_nL[iter], 1u);
                        Ld[pos] = lab;
                    }
                    break;
                }
                s = (s + 1) & (TSZ - 1);
            }
        }
        // warp-aggregated loser self-append
        unsigned lm = __ballot_sync(0xffffffffu, isLoser);
        if (lm) {
            int lane = tid & 31;
            int leader = __ffs(lm) - 1;
            unsigned base = 0;
            if (lane == leader) base = atomicAdd(&g_nL[iter], (unsigned)__popc(lm));
            base = __shfl_sync(0xffffffffu, base, leader);
            if (isLoser) Ld[base + __popc(lm & ((1u << ((unsigned)tid & 31u)) - 1u))] = node;
        }
        if (nd && p == 0) dl[node] = lab;
    }
}

// fused post pass (single block): W histogram over the flagged list, Gram,
// W re-zero, and final-iteration flag clears.
__global__ void __launch_bounds__(1024)
k_post(const float* __restrict__ wts, int labSel, int listSel, int fSel,
       const int* nit, int iter) {
    int lim = get_lim(nit);
    if (iter > lim) return;
    unsigned nn = g_nL[iter];
    if (nn == 0) return;
    const int* L = (listSel == 1) ? g_L1 : g_L2;
    const int* labels = (labSel == 1) ? g_labA : g_labB;
    int tid = threadIdx.x;

    // phase 1: W histogram
    for (unsigned i = tid; i < nn; i += 1024) {
        int node = L[i];
        atomicAdd(&g_W[((size_t)(unsigned)labels[node] << 5) + (node >> 13)], wts[node]);
    }
    __syncthreads();

    // phase 2: Gram  K[g][:] += w*W[lab][:], K[g][g] -= w^2
    __shared__ float S[1024];
    S[tid] = 0.f;
    __syncthreads();
    int lane = tid & 31;
    unsigned warp = tid >> 5;   // 32 warps
    for (unsigned base = warp * 32u; base < nn; base += 1024u) {
        unsigned idx = base + lane;
        bool valid = (idx < nn);
        int lab = 0, gg = 0; float w = 0.f;
        if (valid) {
            int node = L[idx];
            lab = labels[node]; w = wts[node]; gg = node >> 13;
        }
        int cnt = __popc(__ballot_sync(0xffffffffu, valid));
        for (int k0 = 0; k0 < cnt; k0 += 4) {
            float x[4], wk[4]; int gk[4];
#pragma unroll
            for (int k = 0; k < 4; k++) if (k0 + k < cnt) {
                int lb = __shfl_sync(0xffffffffu, lab, k0 + k);
                wk[k] = __shfl_sync(0xffffffffu, w, k0 + k);
                gk[k] = __shfl_sync(0xffffffffu, gg, k0 + k);
                x[k] = g_W[((size_t)(unsigned)lb << 5) + lane];
            }
#pragma unroll
            for (int k = 0; k < 4; k++) if (k0 + k < cnt) {
                float val = wk[k] * x[k];
                if (lane == gk[k]) val -= wk[k] * wk[k];
                atomicAdd(&S[(gk[k] << 5) + lane], val);
            }
        }
    }
    __syncthreads();
    {
        float v = S[tid];
        if (v != 0.f) atomicAdd(&g_K[tid], v);
    }
    __syncthreads();

    // phase 3: restore W zeros; clear flags if this is the final iteration
    int* f = (fSel == 1) ? g_F1i : g_F2i;
    for (unsigned i = tid; i < nn; i += 1024) {
        int node = L[i];
        g_W[((size_t)(unsigned)labels[node] << 5) + (node >> 13)] = 0.f;
        if (iter == lim) f[node] = 0;
    }
}

// final: stream-clear hash table (all blocks) + normalize (block 0) + clear Q
__global__ void __launch_bounds__(1024)
k_clearnorm(float* __restrict__ out, const int* nit) {
    unsigned v = blockIdx.x * 1024 + threadIdx.x;   // grid 256 -> 262144 threads
    int4* tp = (int4*)g_table;
    tp[v] = make_int4(0, 0, 0, 0);
    tp[v + CC] = make_int4(0, 0, 0, 0);
    if (blockIdx.x == 0) {
        int t = threadIdx.x;
        int i = t >> 5, j = t & 31;
        int lim = get_lim(nit);
        __shared__ float d[32];
        float kij = g_K[t] + ((i == j) ? (float)lim * g_Q[i] : 0.f);
        if (i == j) d[i] = kij;
        __syncthreads();
        out[t] = kij / sqrtf(d[i] * d[j]);
        if (t < 32) g_Q[t] = 0.f;
    }
}

// ---------------- host launcher ----------------
extern "C" void kernel_launch(void* const* d_in, const int* in_sizes, int n_in,
                              void* d_out, int out_size) {
    const int*   nbr = (const int*)d_in[0];
    const int*   il  = (const int*)d_in[1];
    const float* wts = (const float*)d_in[2];
    const int*   nit = (n_in >= 4) ? (const int*)d_in[3] : nullptr;
    float* out = (float*)d_out;

    k_init<<<CC / 256, 256>>>(il, wts);
    k_gram0<<<1, 1024>>>();

    // iter 1: src=input, dst=A, flags -> F1, list -> L1
    k_relabel<<<512, 512>>>(nbr, il, 0, 1, 0, 1, 1, nit, 1);
    k_post   <<<1, 1024>>>(wts, 1, 1, 1, nit, 1);
    // iter 2: src=A, dst=B, flags F1 -> F2, list -> L2
    k_relabel<<<512, 512>>>(nbr, il, 1, 2, 1, 2, 2, nit, 2);
    k_post   <<<1, 1024>>>(wts, 2, 2, 2, nit, 2);
    // iter 3: src=B, dst=A, flags F2 -> F1, list -> L1
    k_relabel<<<512, 512>>>(nbr, il, 2, 1, 2, 1, 1, nit, 3);
    k_post   <<<1, 1024>>>(wts, 1, 1, 1, nit, 3);

    k_clearnorm<<<256, 1024>>>(out, nit);
    (void)in_sizes; (void)out_size;
}